// round 12
// baseline (speedup 1.0000x reference)
#include <cuda_runtime.h>
#include <cuda_bf16.h>
#include <cstdint>
#include <cstddef>

constexpr int NN   = 10000;
constexpr int EE   = 320000;
constexpr int DIN  = 512;
constexpr int DOUT = 256;

// ---------------- scratch (__device__ globals; no allocs allowed) ----------
__device__ float g_h[(size_t)NN * DOUT];
__device__ float g_invdeg[NN];
__device__ int   g_degi[NN];
__device__ int   g_off[NN];
__device__ int   g_cur[NN];
__device__ int   g_src[EE];
__device__ int   g_dst[EE];
__device__ int   g_csr[EE];
__device__ int   g_is64;

// bf16 hi/lo split operands (weights in natural [K][N] layout)
__device__ __nv_bfloat16 g_xhi[(size_t)NN * DIN],  g_xlo[(size_t)NN * DIN];
__device__ __nv_bfloat16 g_w0hi[DIN * DOUT],       g_w0lo[DIN * DOUT];
__device__ __nv_bfloat16 g_wl1hi[DOUT * DOUT],     g_wl1lo[DOUT * DOUT];
__device__ __nv_bfloat16 g_wr1hi[DOUT * DOUT],     g_wr1lo[DOUT * DOUT];
__device__ __nv_bfloat16 g_wl2hi[DOUT * DOUT],     g_wl2lo[DOUT * DOUT];
__device__ __nv_bfloat16 g_wr2hi[DOUT * DOUT],     g_wr2lo[DOUT * DOUT];
__device__ __nv_bfloat16 g_hhi[(size_t)NN * DOUT], g_hlo[(size_t)NN * DOUT];
__device__ __nv_bfloat16 g_mhi[(size_t)NN * DOUT], g_mlo[(size_t)NN * DOUT];
__device__ __nv_bfloat16 g_o1hi[(size_t)NN * DOUT], g_o1lo[(size_t)NN * DOUT];

// ---------------------------------------------------------------------------
// Edge-index dtype detection (int64 vs int32).
// ---------------------------------------------------------------------------
__global__ void detect_kernel(const int* __restrict__ raw) {
    int nz = 0;
    for (int i = threadIdx.x; i < 1024; i += blockDim.x)
        nz |= (raw[2 * i + 1] != 0);
    nz = __syncthreads_or(nz);
    if (threadIdx.x == 0) g_is64 = nz ? 0 : 1;
}

// Decode edge_index into int32 src/dst + in-degree histogram.
__global__ void decode_degi_kernel(const int* __restrict__ raw,
                                   int* __restrict__ src, int* __restrict__ dst,
                                   int* __restrict__ degi) {
    int e = blockIdx.x * blockDim.x + threadIdx.x;
    if (e >= EE) return;
    int s, d;
    if (g_is64) { s = raw[2 * e]; d = raw[2 * (EE + e)]; }
    else        { s = raw[e];     d = raw[EE + e]; }
    src[e] = s;
    dst[e] = d;
    atomicAdd(&degi[d], 1);
}

// ---------------------------------------------------------------------------
// bf16 hi/lo split of x and the five weight matrices (one launch).
// ---------------------------------------------------------------------------
__global__ void split_kernel(const float* __restrict__ x,  const float* __restrict__ W0,
                             const float* __restrict__ Wl1, const float* __restrict__ Wr1,
                             const float* __restrict__ Wl2, const float* __restrict__ Wr2) {
    constexpr int S0 = NN * DIN;
    constexpr int S1 = DIN * DOUT;
    constexpr int S2 = DOUT * DOUT;
    int i = blockIdx.x * blockDim.x + threadIdx.x;
    const float* src; __nv_bfloat16 *hi, *lo; int off;
    if      (i < S0)               { src = x;   hi = g_xhi;  lo = g_xlo;  off = i; }
    else if (i < S0 + S1)          { src = W0;  hi = g_w0hi; lo = g_w0lo; off = i - S0; }
    else if (i < S0 + S1 + S2)     { src = Wl1; hi = g_wl1hi; lo = g_wl1lo; off = i - S0 - S1; }
    else if (i < S0 + S1 + 2 * S2) { src = Wr1; hi = g_wr1hi; lo = g_wr1lo; off = i - S0 - S1 - S2; }
    else if (i < S0 + S1 + 3 * S2) { src = Wl2; hi = g_wl2hi; lo = g_wl2lo; off = i - S0 - S1 - 2 * S2; }
    else if (i < S0 + S1 + 4 * S2) { src = Wr2; hi = g_wr2hi; lo = g_wr2lo; off = i - S0 - S1 - 3 * S2; }
    else return;
    float v = src[off];
    __nv_bfloat16 h = __float2bfloat16(v);
    hi[off] = h;
    lo[off] = __float2bfloat16(v - __bfloat162float(h));
}

// ---------------------------------------------------------------------------
// Exclusive scan over degrees -> CSR offsets + cursors + invdeg (1 block).
// ---------------------------------------------------------------------------
__global__ void scan_kernel(const int* __restrict__ degi, int* __restrict__ off,
                            int* __restrict__ cur, float* __restrict__ invdeg) {
    __shared__ int part[256];
    const int t = threadIdx.x;
    const int CH = (NN + 255) / 256;
    const int s0 = t * CH;
    int sum = 0;
    for (int j = 0; j < CH; j++) { int i = s0 + j; if (i < NN) sum += degi[i]; }
    part[t] = sum;
    __syncthreads();
    for (int d = 1; d < 256; d <<= 1) {
        int v = (t >= d) ? part[t - d] : 0;
        __syncthreads();
        part[t] += v;
        __syncthreads();
    }
    int run = (t > 0) ? part[t - 1] : 0;
    for (int j = 0; j < CH; j++) {
        int i = s0 + j;
        if (i < NN) {
            off[i] = run; cur[i] = run;
            int d = degi[i]; run += d;
            invdeg[i] = 1.0f / fmaxf((float)d, 1.0f);
        }
    }
}

__global__ void fill_kernel(const int* __restrict__ src, const int* __restrict__ dst,
                            int* __restrict__ cur, int* __restrict__ csr) {
    int e = blockIdx.x * blockDim.x + threadIdx.x;
    if (e < EE) {
        int p = atomicAdd(&cur[dst[e]], 1);
        csr[p] = src[e];
    }
}

// ---------------------------------------------------------------------------
// CSR gather: mean[i] = invdeg_i * sum h[src(e)], emitted as bf16 hi/lo.
// ---------------------------------------------------------------------------
__global__ void gather_kernel(const float* __restrict__ h,
                              const int* __restrict__ csr,
                              const int* __restrict__ off,
                              const int* __restrict__ degi,
                              const float* __restrict__ invdeg,
                              __nv_bfloat16* __restrict__ mhi,
                              __nv_bfloat16* __restrict__ mlo) {
    const int node = blockIdx.x;
    const int t = threadIdx.x;               // 0..63
    const int base = off[node];
    const int n = degi[node];
    const float4* hp = (const float4*)h;
    float4 acc = make_float4(0.f, 0.f, 0.f, 0.f);
    int e = 0;
    for (; e + 4 <= n; e += 4) {
        int s0 = csr[base + e + 0];
        int s1 = csr[base + e + 1];
        int s2 = csr[base + e + 2];
        int s3 = csr[base + e + 3];
        float4 v0 = hp[(size_t)s0 * 64 + t];
        float4 v1 = hp[(size_t)s1 * 64 + t];
        float4 v2 = hp[(size_t)s2 * 64 + t];
        float4 v3 = hp[(size_t)s3 * 64 + t];
        acc.x += (v0.x + v1.x) + (v2.x + v3.x);
        acc.y += (v0.y + v1.y) + (v2.y + v3.y);
        acc.z += (v0.z + v1.z) + (v2.z + v3.z);
        acc.w += (v0.w + v1.w) + (v2.w + v3.w);
    }
    for (; e < n; e++) {
        int s = csr[base + e];
        float4 v = hp[(size_t)s * 64 + t];
        acc.x += v.x; acc.y += v.y; acc.z += v.z; acc.w += v.w;
    }
    const float s = invdeg[node];
    float o[4] = {acc.x * s, acc.y * s, acc.z * s, acc.w * s};
    __nv_bfloat16 hi[4], lo[4];
#pragma unroll
    for (int j = 0; j < 4; j++) {
        hi[j] = __float2bfloat16(o[j]);
        lo[j] = __float2bfloat16(o[j] - __bfloat162float(hi[j]));
    }
    size_t p = (size_t)node * DOUT + t * 4;
    __nv_bfloat162 a, b;
    a.x = hi[0]; a.y = hi[1]; b.x = hi[2]; b.y = hi[3];
    *(__nv_bfloat162*)(mhi + p) = a; *(__nv_bfloat162*)(mhi + p + 2) = b;
    a.x = lo[0]; a.y = lo[1]; b.x = lo[2]; b.y = lo[3];
    *(__nv_bfloat162*)(mlo + p) = a; *(__nv_bfloat162*)(mlo + p + 2) = b;
}

// ---------------------------------------------------------------------------
// Tensor-core GEMM (bf16x3 split), cp.async 3-stage pipelined.
// Block 32x64 tile, 4 warps (16x32 warp tile), BK=32 -> grid 1252,
// 8 blocks/SM resident = 32 warps/SM (2x the previous occupancy).
// ---------------------------------------------------------------------------
struct PassList {
    const __nv_bfloat16* A[6];
    const __nv_bfloat16* W[6];
};

#define LDSM4(d0, d1, d2, d3, addr) \
    asm volatile("ldmatrix.sync.aligned.m8n8.x4.shared.b16 {%0,%1,%2,%3}, [%4];" \
        : "=r"(d0), "=r"(d1), "=r"(d2), "=r"(d3) : "r"(addr))
#define LDSM4T(d0, d1, d2, d3, addr) \
    asm volatile("ldmatrix.sync.aligned.m8n8.x4.trans.shared.b16 {%0,%1,%2,%3}, [%4];" \
        : "=r"(d0), "=r"(d1), "=r"(d2), "=r"(d3) : "r"(addr))
#define MMA16816(c, a, b0, b1) \
    asm volatile("mma.sync.aligned.m16n8k16.row.col.f32.bf16.bf16.f32 " \
        "{%0,%1,%2,%3}, {%4,%5,%6,%7}, {%8,%9}, {%0,%1,%2,%3};" \
        : "+f"(c[0]), "+f"(c[1]), "+f"(c[2]), "+f"(c[3]) \
        : "r"(a[0]), "r"(a[1]), "r"(a[2]), "r"(a[3]), "r"(b0), "r"(b1))
#define CPA16(dst, src, sz) \
    asm volatile("cp.async.cg.shared.global [%0], [%1], 16, %2;" \
        :: "r"(dst), "l"(src), "r"(sz))
#define CPA_COMMIT() asm volatile("cp.async.commit_group;")

constexpr int ASTR = 40;          // halfs; 80B row stride (conflict-free ldsm)
constexpr int WSTR = 72;          // halfs; 144B row stride (conflict-free ldsm)
constexpr int ABUF = 32 * ASTR;   // halfs per A stage buffer (32 rows x 32 k)
constexpr int WBUF = 32 * WSTR;   // halfs per W stage buffer (32 k x 64 n)
constexpr int PIPE = 3;

template<int K, int NP, bool RELU, bool RES, bool OUTS>
__global__ __launch_bounds__(128, 8)
void gemm_mma(PassList P, const float* __restrict__ bias, const float* __restrict__ res,
              float* __restrict__ C, __nv_bfloat16* __restrict__ Chi,
              __nv_bfloat16* __restrict__ Clo, int M) {
    constexpr int KS = K / 32;
    constexpr int NST = NP * KS;       // 48 for both shapes
    __shared__ __align__(16) __nv_bfloat16 As[PIPE * ABUF];
    __shared__ __align__(16) __nv_bfloat16 Ws[PIPE * WBUF];

    const int tid = threadIdx.x, wid = tid >> 5, lane = tid & 31;
    const int row0 = blockIdx.y * 32, col0 = blockIdx.x * 64;
    const int mb = (wid & 1) * 16, nb = (wid >> 1) * 32;

    float acc[4][4];
#pragma unroll
    for (int nt = 0; nt < 4; nt++)
#pragma unroll
        for (int r = 0; r < 4; r++) acc[nt][r] = 0.f;

    // cp.async mapping (128 threads): A = 32 rows x 32 halfs = 128 chunks
    // (1/thread); W = 32 rows x 64 halfs = 256 chunks (2/thread).
    const int arow = tid >> 2;            // 0..31
    const int achunk = (tid & 3) * 8;     // half offset within 32-wide K tile
    const int wk = tid >> 2;              // 0..31
    const int wn = (tid & 3) * 16;        // two 16B chunks: wn, wn+8

    const uint32_t asu = (uint32_t)__cvta_generic_to_shared(As);
    const uint32_t wsu = (uint32_t)__cvta_generic_to_shared(Ws);

    const int r0g = row0 + arow;
    const int sz0 = (r0g < M) ? 16 : 0;
    const int r0c = (r0g < M) ? r0g : 0;

#define ISSUE(S, BUF) { \
        const int pass = (S) / KS; const int k0 = ((S) - pass * KS) * 32; \
        const __nv_bfloat16* Ap = P.A[pass]; const __nv_bfloat16* Wp = P.W[pass]; \
        CPA16(asu + ((BUF) * ABUF + arow * ASTR + achunk) * 2, \
              Ap + (size_t)r0c * K + k0 + achunk, sz0); \
        CPA16(wsu + ((BUF) * WBUF + wk * WSTR + wn) * 2, \
              Wp + (size_t)(k0 + wk) * DOUT + col0 + wn, 16); \
        CPA16(wsu + ((BUF) * WBUF + wk * WSTR + wn + 8) * 2, \
              Wp + (size_t)(k0 + wk) * DOUT + col0 + wn + 8, 16); \
        CPA_COMMIT(); \
    }

    ISSUE(0, 0);
    ISSUE(1, 1);

    const int r = lane & 7, selr = lane >> 3;
    const uint32_t aoff = (uint32_t)((mb + (selr & 1) * 8 + r) * ASTR + (selr >> 1) * 8) * 2;
    const uint32_t boff = (uint32_t)(((selr & 1) * 8 + r) * WSTR + nb + (selr >> 1) * 8) * 2;

    for (int s = 0; s < NST; s++) {
        if (s + 1 < NST) { asm volatile("cp.async.wait_group 1;"); }
        else             { asm volatile("cp.async.wait_group 0;"); }
        __syncthreads();
        // Safe: buffer (s+2)%3 == (s-1)%3, whose readers all passed this barrier.
        if (s + 2 < NST) ISSUE(s + 2, (s + 2) % PIPE);

        const int buf = s % PIPE;
        const uint32_t abase = asu + buf * ABUF * 2 + aoff;
        const uint32_t wbase = wsu + buf * WBUF * 2 + boff;
#pragma unroll
        for (int kk = 0; kk < 32; kk += 16) {
            uint32_t a[4], bt0[4], bt1[4];
            LDSM4(a[0], a[1], a[2], a[3], abase + kk * 2);
            uint32_t baddr = wbase + kk * WSTR * 2;
            LDSM4T(bt0[0], bt0[1], bt0[2], bt0[3], baddr);
            LDSM4T(bt1[0], bt1[1], bt1[2], bt1[3], baddr + 16 * 2);
            MMA16816(acc[0], a, bt0[0], bt0[1]);
            MMA16816(acc[1], a, bt0[2], bt0[3]);
            MMA16816(acc[2], a, bt1[0], bt1[1]);
            MMA16816(acc[3], a, bt1[2], bt1[3]);
        }
    }
#undef ISSUE

    // epilogue
    const int g = lane >> 2, tig = lane & 3;
#pragma unroll
    for (int half = 0; half < 2; half++) {
        const int row = row0 + mb + g + half * 8;
        if (row >= M) continue;
#pragma unroll
        for (int nt = 0; nt < 4; nt++) {
            const int col = col0 + nb + nt * 8 + tig * 2;
            float v0 = acc[nt][half * 2 + 0] + bias[col];
            float v1 = acc[nt][half * 2 + 1] + bias[col + 1];
            if (RELU) { v0 = fmaxf(v0, 0.f); v1 = fmaxf(v1, 0.f); }
            if (RES) {
                float2 rr = *(const float2*)(res + (size_t)row * DOUT + col);
                v0 += rr.x; v1 += rr.y;
            }
            float2 o; o.x = v0; o.y = v1;
            *(float2*)(C + (size_t)row * DOUT + col) = o;
            if (OUTS) {
                __nv_bfloat16 h0 = __float2bfloat16(v0), h1 = __float2bfloat16(v1);
                __nv_bfloat162 hh; hh.x = h0; hh.y = h1;
                *(__nv_bfloat162*)(Chi + (size_t)row * DOUT + col) = hh;
                __nv_bfloat162 ll;
                ll.x = __float2bfloat16(v0 - __bfloat162float(h0));
                ll.y = __float2bfloat16(v1 - __bfloat162float(h1));
                *(__nv_bfloat162*)(Clo + (size_t)row * DOUT + col) = ll;
            }
        }
    }
}

// ---------------------------------------------------------------------------
// Launch: detect(1) decode(2) split(3) gemm1(4=capture) scan fill
//         gather gemm2 gather gemm3
// ---------------------------------------------------------------------------
extern "C" void kernel_launch(void* const* d_in, const int* in_sizes, int n_in,
                              void* d_out, int out_size) {
    const float* x   = (const float*)d_in[0];
    const int*   ei  = (const int*)d_in[1];
    const float* W0  = (const float*)d_in[2];
    const float* b0  = (const float*)d_in[3];
    const float* Wl1 = (const float*)d_in[4];
    const float* bl1 = (const float*)d_in[5];
    const float* Wr1 = (const float*)d_in[6];
    const float* Wl2 = (const float*)d_in[7];
    const float* bl2 = (const float*)d_in[8];
    const float* Wr2 = (const float*)d_in[9];

    float* out1 = (float*)d_out;
    float* out2 = out1 + (size_t)NN * DOUT;

    float *h, *invdeg;
    int *degi, *off, *cur, *src, *dst, *csr;
    __nv_bfloat16 *xhi, *xlo, *w0hi, *w0lo, *wl1hi, *wl1lo, *wr1hi, *wr1lo;
    __nv_bfloat16 *wl2hi, *wl2lo, *wr2hi, *wr2lo, *hhi, *hlo, *mhi, *mlo, *o1hi, *o1lo;
    cudaGetSymbolAddress((void**)&h,      g_h);
    cudaGetSymbolAddress((void**)&invdeg, g_invdeg);
    cudaGetSymbolAddress((void**)&degi,   g_degi);
    cudaGetSymbolAddress((void**)&off,    g_off);
    cudaGetSymbolAddress((void**)&cur,    g_cur);
    cudaGetSymbolAddress((void**)&src,    g_src);
    cudaGetSymbolAddress((void**)&dst,    g_dst);
    cudaGetSymbolAddress((void**)&csr,    g_csr);
    cudaGetSymbolAddress((void**)&xhi,   g_xhi);   cudaGetSymbolAddress((void**)&xlo,   g_xlo);
    cudaGetSymbolAddress((void**)&w0hi,  g_w0hi);  cudaGetSymbolAddress((void**)&w0lo,  g_w0lo);
    cudaGetSymbolAddress((void**)&wl1hi, g_wl1hi); cudaGetSymbolAddress((void**)&wl1lo, g_wl1lo);
    cudaGetSymbolAddress((void**)&wr1hi, g_wr1hi); cudaGetSymbolAddress((void**)&wr1lo, g_wr1lo);
    cudaGetSymbolAddress((void**)&wl2hi, g_wl2hi); cudaGetSymbolAddress((void**)&wl2lo, g_wl2lo);
    cudaGetSymbolAddress((void**)&wr2hi, g_wr2hi); cudaGetSymbolAddress((void**)&wr2lo, g_wr2lo);
    cudaGetSymbolAddress((void**)&hhi,   g_hhi);   cudaGetSymbolAddress((void**)&hlo,   g_hlo);
    cudaGetSymbolAddress((void**)&mhi,   g_mhi);   cudaGetSymbolAddress((void**)&mlo,   g_mlo);
    cudaGetSymbolAddress((void**)&o1hi,  g_o1hi);  cudaGetSymbolAddress((void**)&o1lo,  g_o1lo);

    const int EB = (EE + 255) / 256;
    const int SPLIT_N = NN * DIN + DIN * DOUT + 4 * DOUT * DOUT;
    dim3 mgrid(DOUT / 64, (NN + 31) / 32);    // (4, 313) = 1252 blocks

    detect_kernel<<<1, 256>>>(ei);                                     // k1
    cudaMemsetAsync(degi, 0, NN * sizeof(int));
    decode_degi_kernel<<<EB, 256>>>(ei, src, dst, degi);               // k2
    split_kernel<<<(SPLIT_N + 255) / 256, 256>>>(x, W0, Wl1, Wr1, Wl2, Wr2);  // k3

    // gemm1: h = x @ W0 + b0  (bf16x3: 3 passes, K=512) — k4, capture target
    {
        PassList P{};
        P.A[0] = xhi; P.W[0] = w0hi;
        P.A[1] = xlo; P.W[1] = w0hi;
        P.A[2] = xhi; P.W[2] = w0lo;
        gemm_mma<DIN, 3, false, false, true><<<mgrid, 128>>>(
            P, b0, nullptr, h, hhi, hlo, NN);
    }

    scan_kernel<<<1, 256>>>(degi, off, cur, invdeg);                   // k5
    fill_kernel<<<EB, 256>>>(src, dst, cur, csr);                      // k6

    // conv1
    gather_kernel<<<NN, 64>>>(h, csr, off, degi, invdeg, mhi, mlo);
    {
        PassList P{};
        P.A[0] = mhi; P.W[0] = wl1hi;
        P.A[1] = mlo; P.W[1] = wl1hi;
        P.A[2] = mhi; P.W[2] = wl1lo;
        P.A[3] = hhi; P.W[3] = wr1hi;
        P.A[4] = hlo; P.W[4] = wr1hi;
        P.A[5] = hhi; P.W[5] = wr1lo;
        gemm_mma<DOUT, 6, true, true, true><<<mgrid, 128>>>(
            P, bl1, h, out1, o1hi, o1lo, NN);
    }

    // conv2
    gather_kernel<<<NN, 64>>>(out1, csr, off, degi, invdeg, mhi, mlo);
    {
        PassList P{};
        P.A[0] = mhi;  P.W[0] = wl2hi;
        P.A[1] = mlo;  P.W[1] = wl2hi;
        P.A[2] = mhi;  P.W[2] = wl2lo;
        P.A[3] = o1hi; P.W[3] = wr2hi;
        P.A[4] = o1lo; P.W[4] = wr2hi;
        P.A[5] = o1hi; P.W[5] = wr2lo;
        gemm_mma<DOUT, 6, false, true, false><<<mgrid, 128>>>(
            P, bl2, out1, out2, nullptr, nullptr, NN);
    }
}

// round 13
// speedup vs baseline: 1.2110x; 1.2110x over previous
#include <cuda_runtime.h>
#include <cuda_bf16.h>
#include <cstdint>
#include <cstddef>

constexpr int NN   = 10000;
constexpr int EE   = 320000;
constexpr int DIN  = 512;
constexpr int DOUT = 256;

// ---------------- scratch (__device__ globals; no allocs allowed) ----------
__device__ float g_h[(size_t)NN * DOUT];
__device__ float g_tmp[(size_t)NN * DOUT];
__device__ float g_invdeg[NN];
__device__ int   g_degi[NN];
__device__ int   g_off[NN];
__device__ int   g_cur[NN];
__device__ int   g_src[EE];
__device__ int   g_dst[EE];
__device__ int   g_csr[EE];
__device__ int   g_is64;

// bf16 hi/lo split operands (weights in natural [K][N] layout)
__device__ __nv_bfloat16 g_xhi[(size_t)NN * DIN],  g_xlo[(size_t)NN * DIN];
__device__ __nv_bfloat16 g_w0hi[DIN * DOUT],       g_w0lo[DIN * DOUT];
__device__ __nv_bfloat16 g_wl1hi[DOUT * DOUT],     g_wl1lo[DOUT * DOUT];
__device__ __nv_bfloat16 g_wr1hi[DOUT * DOUT],     g_wr1lo[DOUT * DOUT];
__device__ __nv_bfloat16 g_wl2hi[DOUT * DOUT],     g_wl2lo[DOUT * DOUT];
__device__ __nv_bfloat16 g_wr2hi[DOUT * DOUT],     g_wr2lo[DOUT * DOUT];
__device__ __nv_bfloat16 g_hhi[(size_t)NN * DOUT], g_hlo[(size_t)NN * DOUT];
__device__ __nv_bfloat16 g_mhi[(size_t)NN * DOUT], g_mlo[(size_t)NN * DOUT];
__device__ __nv_bfloat16 g_o1hi[(size_t)NN * DOUT], g_o1lo[(size_t)NN * DOUT];

// ---------------------------------------------------------------------------
// Edge-index dtype detection (int64 vs int32).
// ---------------------------------------------------------------------------
__global__ void detect_kernel(const int* __restrict__ raw) {
    int nz = 0;
    for (int i = threadIdx.x; i < 1024; i += blockDim.x)
        nz |= (raw[2 * i + 1] != 0);
    nz = __syncthreads_or(nz);
    if (threadIdx.x == 0) g_is64 = nz ? 0 : 1;
}

// Decode edge_index into int32 src/dst + in-degree histogram.
__global__ void decode_degi_kernel(const int* __restrict__ raw,
                                   int* __restrict__ src, int* __restrict__ dst,
                                   int* __restrict__ degi) {
    int e = blockIdx.x * blockDim.x + threadIdx.x;
    if (e >= EE) return;
    int s, d;
    if (g_is64) { s = raw[2 * e]; d = raw[2 * (EE + e)]; }
    else        { s = raw[e];     d = raw[EE + e]; }
    src[e] = s;
    dst[e] = d;
    atomicAdd(&degi[d], 1);
}

// ---------------------------------------------------------------------------
// bf16 hi/lo split of x and the five weight matrices (one launch).
// ---------------------------------------------------------------------------
__global__ void split_kernel(const float* __restrict__ x,  const float* __restrict__ W0,
                             const float* __restrict__ Wl1, const float* __restrict__ Wr1,
                             const float* __restrict__ Wl2, const float* __restrict__ Wr2) {
    constexpr int S0 = NN * DIN;
    constexpr int S1 = DIN * DOUT;
    constexpr int S2 = DOUT * DOUT;
    int i = blockIdx.x * blockDim.x + threadIdx.x;
    const float* src; __nv_bfloat16 *hi, *lo; int off;
    if      (i < S0)               { src = x;   hi = g_xhi;  lo = g_xlo;  off = i; }
    else if (i < S0 + S1)          { src = W0;  hi = g_w0hi; lo = g_w0lo; off = i - S0; }
    else if (i < S0 + S1 + S2)     { src = Wl1; hi = g_wl1hi; lo = g_wl1lo; off = i - S0 - S1; }
    else if (i < S0 + S1 + 2 * S2) { src = Wr1; hi = g_wr1hi; lo = g_wr1lo; off = i - S0 - S1 - S2; }
    else if (i < S0 + S1 + 3 * S2) { src = Wl2; hi = g_wl2hi; lo = g_wl2lo; off = i - S0 - S1 - 2 * S2; }
    else if (i < S0 + S1 + 4 * S2) { src = Wr2; hi = g_wr2hi; lo = g_wr2lo; off = i - S0 - S1 - 3 * S2; }
    else return;
    float v = src[off];
    __nv_bfloat16 h = __float2bfloat16(v);
    hi[off] = h;
    lo[off] = __float2bfloat16(v - __bfloat162float(h));
}

// ---------------------------------------------------------------------------
// Exclusive scan over degrees -> CSR offsets + cursors + invdeg (1 block).
// ---------------------------------------------------------------------------
__global__ void scan_kernel(const int* __restrict__ degi, int* __restrict__ off,
                            int* __restrict__ cur, float* __restrict__ invdeg) {
    __shared__ int part[256];
    const int t = threadIdx.x;
    const int CH = (NN + 255) / 256;
    const int s0 = t * CH;
    int sum = 0;
    for (int j = 0; j < CH; j++) { int i = s0 + j; if (i < NN) sum += degi[i]; }
    part[t] = sum;
    __syncthreads();
    for (int d = 1; d < 256; d <<= 1) {
        int v = (t >= d) ? part[t - d] : 0;
        __syncthreads();
        part[t] += v;
        __syncthreads();
    }
    int run = (t > 0) ? part[t - 1] : 0;
    for (int j = 0; j < CH; j++) {
        int i = s0 + j;
        if (i < NN) {
            off[i] = run; cur[i] = run;
            int d = degi[i]; run += d;
            invdeg[i] = 1.0f / fmaxf((float)d, 1.0f);
        }
    }
}

__global__ void fill_kernel(const int* __restrict__ src, const int* __restrict__ dst,
                            int* __restrict__ cur, int* __restrict__ csr) {
    int e = blockIdx.x * blockDim.x + threadIdx.x;
    if (e < EE) {
        int p = atomicAdd(&cur[dst[e]], 1);
        csr[p] = src[e];
    }
}

// ---------------------------------------------------------------------------
// CSR gather: mean[i] = invdeg_i * sum h[src(e)], emitted as bf16 hi/lo.
// ---------------------------------------------------------------------------
__global__ void gather_kernel(const float* __restrict__ h,
                              const int* __restrict__ csr,
                              const int* __restrict__ off,
                              const int* __restrict__ degi,
                              const float* __restrict__ invdeg,
                              __nv_bfloat16* __restrict__ mhi,
                              __nv_bfloat16* __restrict__ mlo) {
    const int node = blockIdx.x;
    const int t = threadIdx.x;               // 0..63
    const int base = off[node];
    const int n = degi[node];
    const float4* hp = (const float4*)h;
    float4 acc = make_float4(0.f, 0.f, 0.f, 0.f);
    int e = 0;
    for (; e + 4 <= n; e += 4) {
        int s0 = csr[base + e + 0];
        int s1 = csr[base + e + 1];
        int s2 = csr[base + e + 2];
        int s3 = csr[base + e + 3];
        float4 v0 = hp[(size_t)s0 * 64 + t];
        float4 v1 = hp[(size_t)s1 * 64 + t];
        float4 v2 = hp[(size_t)s2 * 64 + t];
        float4 v3 = hp[(size_t)s3 * 64 + t];
        acc.x += (v0.x + v1.x) + (v2.x + v3.x);
        acc.y += (v0.y + v1.y) + (v2.y + v3.y);
        acc.z += (v0.z + v1.z) + (v2.z + v3.z);
        acc.w += (v0.w + v1.w) + (v2.w + v3.w);
    }
    for (; e < n; e++) {
        int s = csr[base + e];
        float4 v = hp[(size_t)s * 64 + t];
        acc.x += v.x; acc.y += v.y; acc.z += v.z; acc.w += v.w;
    }
    const float s = invdeg[node];
    float o[4] = {acc.x * s, acc.y * s, acc.z * s, acc.w * s};
    __nv_bfloat16 hi[4], lo[4];
#pragma unroll
    for (int j = 0; j < 4; j++) {
        hi[j] = __float2bfloat16(o[j]);
        lo[j] = __float2bfloat16(o[j] - __bfloat162float(hi[j]));
    }
    size_t p = (size_t)node * DOUT + t * 4;
    __nv_bfloat162 a, b;
    a.x = hi[0]; a.y = hi[1]; b.x = hi[2]; b.y = hi[3];
    *(__nv_bfloat162*)(mhi + p) = a; *(__nv_bfloat162*)(mhi + p + 2) = b;
    a.x = lo[0]; a.y = lo[1]; b.x = lo[2]; b.y = lo[3];
    *(__nv_bfloat162*)(mlo + p) = a; *(__nv_bfloat162*)(mlo + p + 2) = b;
}

// ---------------------------------------------------------------------------
// Tensor-core GEMM (bf16x3 split), cp.async 3-stage pipelined (R8 core).
// Block 64x64, 4 warps (32x32 warp tile), BK=32, single sync per stage.
//   C = op( sum_p A_p@W_p [+ bias] [+ add] ) [relu] [+ res]; optional hi/lo out.
// ---------------------------------------------------------------------------
struct PassList {
    const __nv_bfloat16* A[3];
    const __nv_bfloat16* W[3];
};

#define LDSM4(d0, d1, d2, d3, addr) \
    asm volatile("ldmatrix.sync.aligned.m8n8.x4.shared.b16 {%0,%1,%2,%3}, [%4];" \
        : "=r"(d0), "=r"(d1), "=r"(d2), "=r"(d3) : "r"(addr))
#define LDSM4T(d0, d1, d2, d3, addr) \
    asm volatile("ldmatrix.sync.aligned.m8n8.x4.trans.shared.b16 {%0,%1,%2,%3}, [%4];" \
        : "=r"(d0), "=r"(d1), "=r"(d2), "=r"(d3) : "r"(addr))
#define MMA16816(c, a, b0, b1) \
    asm volatile("mma.sync.aligned.m16n8k16.row.col.f32.bf16.bf16.f32 " \
        "{%0,%1,%2,%3}, {%4,%5,%6,%7}, {%8,%9}, {%0,%1,%2,%3};" \
        : "+f"(c[0]), "+f"(c[1]), "+f"(c[2]), "+f"(c[3]) \
        : "r"(a[0]), "r"(a[1]), "r"(a[2]), "r"(a[3]), "r"(b0), "r"(b1))
#define CPA16(dst, src, sz) \
    asm volatile("cp.async.cg.shared.global [%0], [%1], 16, %2;" \
        :: "r"(dst), "l"(src), "r"(sz))
#define CPA_COMMIT() asm volatile("cp.async.commit_group;")

constexpr int ASTR = 40;          // halfs; 80B row stride (conflict-free ldsm)
constexpr int WSTR = 72;          // halfs; 144B row stride (conflict-free ldsm)
constexpr int ABUF = 64 * ASTR;
constexpr int WBUF = 32 * WSTR;
constexpr int PIPE = 3;

template<int K, int NP, bool BIAS, bool ADD, bool RELU, bool RES, bool OUTS>
__global__ __launch_bounds__(128)
void gemm_mma(PassList P, const float* __restrict__ bias, const float* __restrict__ add,
              const float* __restrict__ res,
              float* __restrict__ C, __nv_bfloat16* __restrict__ Chi,
              __nv_bfloat16* __restrict__ Clo, int M) {
    constexpr int KS = K / 32;
    constexpr int NST = NP * KS;
    __shared__ __align__(16) __nv_bfloat16 As[PIPE * ABUF];
    __shared__ __align__(16) __nv_bfloat16 Ws[PIPE * WBUF];

    const int tid = threadIdx.x, wid = tid >> 5, lane = tid & 31;
    const int row0 = blockIdx.y * 64, col0 = blockIdx.x * 64;
    const int mb = (wid & 1) * 32, nb = (wid >> 1) * 32;

    float acc[2][4][4];
#pragma unroll
    for (int mt = 0; mt < 2; mt++)
#pragma unroll
        for (int nt = 0; nt < 4; nt++)
#pragma unroll
            for (int r = 0; r < 4; r++) acc[mt][nt][r] = 0.f;

    const int arow = tid >> 2;
    const int achunk = (tid & 3) * 8;
    const int wk = tid >> 2;
    const int wn = (tid & 3) * 16;

    const uint32_t asu = (uint32_t)__cvta_generic_to_shared(As);
    const uint32_t wsu = (uint32_t)__cvta_generic_to_shared(Ws);

    const int r0g = row0 + arow, r1g = r0g + 32;
    const int sz0 = (r0g < M) ? 16 : 0, sz1 = (r1g < M) ? 16 : 0;
    const int r0c = (r0g < M) ? r0g : 0, r1c = (r1g < M) ? r1g : 0;

#define ISSUE(S, BUF) { \
        const int pass = (S) / KS; const int k0 = ((S) - pass * KS) * 32; \
        const __nv_bfloat16* Ap = P.A[pass]; const __nv_bfloat16* Wp = P.W[pass]; \
        CPA16(asu + ((BUF) * ABUF + arow * ASTR + achunk) * 2, \
              Ap + (size_t)r0c * K + k0 + achunk, sz0); \
        CPA16(asu + ((BUF) * ABUF + (arow + 32) * ASTR + achunk) * 2, \
              Ap + (size_t)r1c * K + k0 + achunk, sz1); \
        CPA16(wsu + ((BUF) * WBUF + wk * WSTR + wn) * 2, \
              Wp + (size_t)(k0 + wk) * DOUT + col0 + wn, 16); \
        CPA16(wsu + ((BUF) * WBUF + wk * WSTR + wn + 8) * 2, \
              Wp + (size_t)(k0 + wk) * DOUT + col0 + wn + 8, 16); \
        CPA_COMMIT(); \
    }

    ISSUE(0, 0);
    ISSUE(1, 1);

    const int r = lane & 7, selr = lane >> 3;
    const uint32_t aoff = (uint32_t)((mb + (selr & 1) * 8 + r) * ASTR + (selr >> 1) * 8) * 2;
    const uint32_t boff = (uint32_t)(((selr & 1) * 8 + r) * WSTR + nb + (selr >> 1) * 8) * 2;

    for (int s = 0; s < NST; s++) {
        if (s + 1 < NST) { asm volatile("cp.async.wait_group 1;"); }
        else             { asm volatile("cp.async.wait_group 0;"); }
        __syncthreads();
        if (s + 2 < NST) ISSUE(s + 2, (s + 2) % PIPE);

        const int buf = s % PIPE;
        const uint32_t abase = asu + buf * ABUF * 2 + aoff;
        const uint32_t wbase = wsu + buf * WBUF * 2 + boff;
#pragma unroll
        for (int kk = 0; kk < 32; kk += 16) {
            uint32_t a[2][4], bt0[4], bt1[4];
            uint32_t aaddr = abase + kk * 2;
            LDSM4(a[0][0], a[0][1], a[0][2], a[0][3], aaddr);
            LDSM4(a[1][0], a[1][1], a[1][2], a[1][3], aaddr + 16 * ASTR * 2);
            uint32_t baddr = wbase + kk * WSTR * 2;
            LDSM4T(bt0[0], bt0[1], bt0[2], bt0[3], baddr);
            LDSM4T(bt1[0], bt1[1], bt1[2], bt1[3], baddr + 16 * 2);
#pragma unroll
            for (int mt = 0; mt < 2; mt++) {
                MMA16816(acc[mt][0], a[mt], bt0[0], bt0[1]);
                MMA16816(acc[mt][1], a[mt], bt0[2], bt0[3]);
                MMA16816(acc[mt][2], a[mt], bt1[0], bt1[1]);
                MMA16816(acc[mt][3], a[mt], bt1[2], bt1[3]);
            }
        }
    }
#undef ISSUE

    // epilogue: [+bias] [+add] [relu] [+res]
    const int g = lane >> 2, tig = lane & 3;
#pragma unroll
    for (int mt = 0; mt < 2; mt++) {
#pragma unroll
        for (int half = 0; half < 2; half++) {
            const int row = row0 + mb + mt * 16 + g + half * 8;
            if (row >= M) continue;
#pragma unroll
            for (int nt = 0; nt < 4; nt++) {
                const int col = col0 + nb + nt * 8 + tig * 2;
                float v0 = acc[mt][nt][half * 2 + 0];
                float v1 = acc[mt][nt][half * 2 + 1];
                if (BIAS) { v0 += bias[col]; v1 += bias[col + 1]; }
                if (ADD) {
                    float2 aa = *(const float2*)(add + (size_t)row * DOUT + col);
                    v0 += aa.x; v1 += aa.y;
                }
                if (RELU) { v0 = fmaxf(v0, 0.f); v1 = fmaxf(v1, 0.f); }
                if (RES) {
                    float2 rr = *(const float2*)(res + (size_t)row * DOUT + col);
                    v0 += rr.x; v1 += rr.y;
                }
                float2 o; o.x = v0; o.y = v1;
                *(float2*)(C + (size_t)row * DOUT + col) = o;
                if (OUTS) {
                    __nv_bfloat16 h0 = __float2bfloat16(v0), h1 = __float2bfloat16(v1);
                    __nv_bfloat162 hh; hh.x = h0; hh.y = h1;
                    *(__nv_bfloat162*)(Chi + (size_t)row * DOUT + col) = hh;
                    __nv_bfloat162 ll;
                    ll.x = __float2bfloat16(v0 - __bfloat162float(h0));
                    ll.y = __float2bfloat16(v1 - __bfloat162float(h1));
                    *(__nv_bfloat162*)(Clo + (size_t)row * DOUT + col) = ll;
                }
            }
        }
    }
}

// ---------------------------------------------------------------------------
// Launch graph (dual-stream):
//   main: detect decode | split gemm1 | tmp1=h@Wr1 | gemm2b | tmp2=o1@Wr2 | gemm3b
//   s2:             \-> scan fill      \-> gather1 -/   \-> gather2 -/
// ---------------------------------------------------------------------------
extern "C" void kernel_launch(void* const* d_in, const int* in_sizes, int n_in,
                              void* d_out, int out_size) {
    const float* x   = (const float*)d_in[0];
    const int*   ei  = (const int*)d_in[1];
    const float* W0  = (const float*)d_in[2];
    const float* b0  = (const float*)d_in[3];
    const float* Wl1 = (const float*)d_in[4];
    const float* bl1 = (const float*)d_in[5];
    const float* Wr1 = (const float*)d_in[6];
    const float* Wl2 = (const float*)d_in[7];
    const float* bl2 = (const float*)d_in[8];
    const float* Wr2 = (const float*)d_in[9];

    float* out1 = (float*)d_out;
    float* out2 = out1 + (size_t)NN * DOUT;

    float *h, *tmp, *invdeg;
    int *degi, *off, *cur, *src, *dst, *csr;
    __nv_bfloat16 *xhi, *xlo, *w0hi, *w0lo, *wl1hi, *wl1lo, *wr1hi, *wr1lo;
    __nv_bfloat16 *wl2hi, *wl2lo, *wr2hi, *wr2lo, *hhi, *hlo, *mhi, *mlo, *o1hi, *o1lo;
    cudaGetSymbolAddress((void**)&h,      g_h);
    cudaGetSymbolAddress((void**)&tmp,    g_tmp);
    cudaGetSymbolAddress((void**)&invdeg, g_invdeg);
    cudaGetSymbolAddress((void**)&degi,   g_degi);
    cudaGetSymbolAddress((void**)&off,    g_off);
    cudaGetSymbolAddress((void**)&cur,    g_cur);
    cudaGetSymbolAddress((void**)&src,    g_src);
    cudaGetSymbolAddress((void**)&dst,    g_dst);
    cudaGetSymbolAddress((void**)&csr,    g_csr);
    cudaGetSymbolAddress((void**)&xhi,   g_xhi);   cudaGetSymbolAddress((void**)&xlo,   g_xlo);
    cudaGetSymbolAddress((void**)&w0hi,  g_w0hi);  cudaGetSymbolAddress((void**)&w0lo,  g_w0lo);
    cudaGetSymbolAddress((void**)&wl1hi, g_wl1hi); cudaGetSymbolAddress((void**)&wl1lo, g_wl1lo);
    cudaGetSymbolAddress((void**)&wr1hi, g_wr1hi); cudaGetSymbolAddress((void**)&wr1lo, g_wr1lo);
    cudaGetSymbolAddress((void**)&wl2hi, g_wl2hi); cudaGetSymbolAddress((void**)&wl2lo, g_wl2lo);
    cudaGetSymbolAddress((void**)&wr2hi, g_wr2hi); cudaGetSymbolAddress((void**)&wr2lo, g_wr2lo);
    cudaGetSymbolAddress((void**)&hhi,   g_hhi);   cudaGetSymbolAddress((void**)&hlo,   g_hlo);
    cudaGetSymbolAddress((void**)&mhi,   g_mhi);   cudaGetSymbolAddress((void**)&mlo,   g_mlo);
    cudaGetSymbolAddress((void**)&o1hi,  g_o1hi);  cudaGetSymbolAddress((void**)&o1lo,  g_o1lo);

    // Static side stream + events (created on first, uncaptured call).
    static cudaStream_t s2 = nullptr;
    static cudaEvent_t eA = nullptr, eH = nullptr, eG1 = nullptr, eO1 = nullptr, eG2 = nullptr;
    if (!s2) {
        cudaStreamCreateWithFlags(&s2, cudaStreamNonBlocking);
        cudaEventCreateWithFlags(&eA,  cudaEventDisableTiming);
        cudaEventCreateWithFlags(&eH,  cudaEventDisableTiming);
        cudaEventCreateWithFlags(&eG1, cudaEventDisableTiming);
        cudaEventCreateWithFlags(&eO1, cudaEventDisableTiming);
        cudaEventCreateWithFlags(&eG2, cudaEventDisableTiming);
    }

    const int EB = (EE + 255) / 256;
    const int SPLIT_N = NN * DIN + DIN * DOUT + 4 * DOUT * DOUT;
    dim3 mgrid(DOUT / 64, (NN + 63) / 64);    // (4, 157) = 628 blocks

    // main: edge decode
    detect_kernel<<<1, 256>>>(ei);
    cudaMemsetAsync(degi, 0, NN * sizeof(int));
    decode_degi_kernel<<<EB, 256>>>(ei, src, dst, degi);
    cudaEventRecord(eA, 0);

    // s2: CSR build (overlaps split + gemm1)
    cudaStreamWaitEvent(s2, eA, 0);
    scan_kernel<<<1, 256, 0, s2>>>(degi, off, cur, invdeg);
    fill_kernel<<<EB, 256, 0, s2>>>(src, dst, cur, csr);

    // main: split + gemm1 (h = x@W0 + b0)
    split_kernel<<<(SPLIT_N + 255) / 256, 256>>>(x, W0, Wl1, Wr1, Wl2, Wr2);
    {
        PassList P{};
        P.A[0] = xhi; P.W[0] = w0hi;
        P.A[1] = xlo; P.W[1] = w0hi;
        P.A[2] = xhi; P.W[2] = w0lo;
        gemm_mma<DIN, 3, true, false, false, false, true><<<mgrid, 128>>>(
            P, b0, nullptr, nullptr, h, hhi, hlo, NN);
    }
    cudaEventRecord(eH, 0);

    // s2: gather1 (needs h + CSR) || main: tmp1 = h@Wr1
    cudaStreamWaitEvent(s2, eH, 0);
    gather_kernel<<<NN, 64, 0, s2>>>(h, csr, off, degi, invdeg, mhi, mlo);
    cudaEventRecord(eG1, s2);
    {
        PassList P{};
        P.A[0] = hhi; P.W[0] = wr1hi;
        P.A[1] = hlo; P.W[1] = wr1hi;
        P.A[2] = hhi; P.W[2] = wr1lo;
        gemm_mma<DOUT, 3, false, false, false, false, false><<<mgrid, 128>>>(
            P, nullptr, nullptr, nullptr, tmp, nullptr, nullptr, NN);
    }

    // main: out1 = relu(mean@Wl1 + bl1 + tmp1) + h
    cudaStreamWaitEvent(0, eG1, 0);
    {
        PassList P{};
        P.A[0] = mhi; P.W[0] = wl1hi;
        P.A[1] = mlo; P.W[1] = wl1hi;
        P.A[2] = mhi; P.W[2] = wl1lo;
        gemm_mma<DOUT, 3, true, true, true, true, true><<<mgrid, 128>>>(
            P, bl1, tmp, h, out1, o1hi, o1lo, NN);
    }
    cudaEventRecord(eO1, 0);

    // s2: gather2 (needs out1 + CSR) || main: tmp2 = out1@Wr2
    cudaStreamWaitEvent(s2, eO1, 0);
    gather_kernel<<<NN, 64, 0, s2>>>(out1, csr, off, degi, invdeg, mhi, mlo);
    cudaEventRecord(eG2, s2);
    {
        PassList P{};
        P.A[0] = o1hi; P.W[0] = wr2hi;
        P.A[1] = o1lo; P.W[1] = wr2hi;
        P.A[2] = o1hi; P.W[2] = wr2lo;
        gemm_mma<DOUT, 3, false, false, false, false, false><<<mgrid, 128>>>(
            P, nullptr, nullptr, nullptr, tmp, nullptr, nullptr, NN);
    }

    // main: out2 = mean@Wl2 + bl2 + tmp2 + out1
    cudaStreamWaitEvent(0, eG2, 0);
    {
        PassList P{};
        P.A[0] = mhi; P.W[0] = wl2hi;
        P.A[1] = mlo; P.W[1] = wl2hi;
        P.A[2] = mhi; P.W[2] = wl2lo;
        gemm_mma<DOUT, 3, true, true, false, true, false><<<mgrid, 128>>>(
            P, bl2, tmp, out1, out2, nullptr, nullptr, NN);
    }
}

// round 14
// speedup vs baseline: 1.4762x; 1.2190x over previous
#include <cuda_runtime.h>
#include <cuda_bf16.h>
#include <cstdint>
#include <cstddef>

constexpr int NN   = 10000;
constexpr int EE   = 320000;
constexpr int DIN  = 512;
constexpr int DOUT = 256;

// ---------------- scratch (__device__ globals; no allocs allowed) ----------
__device__ float g_h[(size_t)NN * DOUT];
__device__ float g_tmp[(size_t)NN * DOUT];
__device__ float g_invdeg[NN];
__device__ int   g_degi[NN];
__device__ int   g_off[NN];
__device__ int   g_cur[NN];
__device__ int   g_src[EE];
__device__ int   g_dst[EE];
__device__ int   g_csr[EE];
__device__ int   g_is64;

// bf16 hi/lo split operands (weights in natural [K][N] layout)
__device__ __nv_bfloat16 g_xhi[(size_t)NN * DIN],  g_xlo[(size_t)NN * DIN];
__device__ __nv_bfloat16 g_w0hi[DIN * DOUT],       g_w0lo[DIN * DOUT];
__device__ __nv_bfloat16 g_wl1hi[DOUT * DOUT],     g_wl1lo[DOUT * DOUT];
__device__ __nv_bfloat16 g_wr1hi[DOUT * DOUT],     g_wr1lo[DOUT * DOUT];
__device__ __nv_bfloat16 g_wl2hi[DOUT * DOUT],     g_wl2lo[DOUT * DOUT];
__device__ __nv_bfloat16 g_wr2hi[DOUT * DOUT],     g_wr2lo[DOUT * DOUT];
__device__ __nv_bfloat16 g_hhi[(size_t)NN * DOUT], g_hlo[(size_t)NN * DOUT];
__device__ __nv_bfloat16 g_mhi[(size_t)NN * DOUT], g_mlo[(size_t)NN * DOUT];
__device__ __nv_bfloat16 g_o1hi[(size_t)NN * DOUT], g_o1lo[(size_t)NN * DOUT];

// ---------------------------------------------------------------------------
// Edge-index dtype detection (int64 vs int32).
// ---------------------------------------------------------------------------
__global__ void detect_kernel(const int* __restrict__ raw) {
    int nz = 0;
    for (int i = threadIdx.x; i < 1024; i += blockDim.x)
        nz |= (raw[2 * i + 1] != 0);
    nz = __syncthreads_or(nz);
    if (threadIdx.x == 0) g_is64 = nz ? 0 : 1;
}

// Decode edge_index into int32 src/dst + in-degree histogram.
__global__ void decode_degi_kernel(const int* __restrict__ raw,
                                   int* __restrict__ src, int* __restrict__ dst,
                                   int* __restrict__ degi) {
    int e = blockIdx.x * blockDim.x + threadIdx.x;
    if (e >= EE) return;
    int s, d;
    if (g_is64) { s = raw[2 * e]; d = raw[2 * (EE + e)]; }
    else        { s = raw[e];     d = raw[EE + e]; }
    src[e] = s;
    dst[e] = d;
    atomicAdd(&degi[d], 1);
}

// ---------------------------------------------------------------------------
// bf16 hi/lo split of x and the five weight matrices (one launch).
// ---------------------------------------------------------------------------
__global__ void split_kernel(const float* __restrict__ x,  const float* __restrict__ W0,
                             const float* __restrict__ Wl1, const float* __restrict__ Wr1,
                             const float* __restrict__ Wl2, const float* __restrict__ Wr2) {
    constexpr int S0 = NN * DIN;
    constexpr int S1 = DIN * DOUT;
    constexpr int S2 = DOUT * DOUT;
    int i = blockIdx.x * blockDim.x + threadIdx.x;
    const float* src; __nv_bfloat16 *hi, *lo; int off;
    if      (i < S0)               { src = x;   hi = g_xhi;  lo = g_xlo;  off = i; }
    else if (i < S0 + S1)          { src = W0;  hi = g_w0hi; lo = g_w0lo; off = i - S0; }
    else if (i < S0 + S1 + S2)     { src = Wl1; hi = g_wl1hi; lo = g_wl1lo; off = i - S0 - S1; }
    else if (i < S0 + S1 + 2 * S2) { src = Wr1; hi = g_wr1hi; lo = g_wr1lo; off = i - S0 - S1 - S2; }
    else if (i < S0 + S1 + 3 * S2) { src = Wl2; hi = g_wl2hi; lo = g_wl2lo; off = i - S0 - S1 - 2 * S2; }
    else if (i < S0 + S1 + 4 * S2) { src = Wr2; hi = g_wr2hi; lo = g_wr2lo; off = i - S0 - S1 - 3 * S2; }
    else return;
    float v = src[off];
    __nv_bfloat16 h = __float2bfloat16(v);
    hi[off] = h;
    lo[off] = __float2bfloat16(v - __bfloat162float(h));
}

// ---------------------------------------------------------------------------
// Exclusive scan over degrees -> CSR offsets + cursors + invdeg (1 block).
// ---------------------------------------------------------------------------
__global__ void scan_kernel(const int* __restrict__ degi, int* __restrict__ off,
                            int* __restrict__ cur, float* __restrict__ invdeg) {
    __shared__ int part[256];
    const int t = threadIdx.x;
    const int CH = (NN + 255) / 256;
    const int s0 = t * CH;
    int sum = 0;
    for (int j = 0; j < CH; j++) { int i = s0 + j; if (i < NN) sum += degi[i]; }
    part[t] = sum;
    __syncthreads();
    for (int d = 1; d < 256; d <<= 1) {
        int v = (t >= d) ? part[t - d] : 0;
        __syncthreads();
        part[t] += v;
        __syncthreads();
    }
    int run = (t > 0) ? part[t - 1] : 0;
    for (int j = 0; j < CH; j++) {
        int i = s0 + j;
        if (i < NN) {
            off[i] = run; cur[i] = run;
            int d = degi[i]; run += d;
            invdeg[i] = 1.0f / fmaxf((float)d, 1.0f);
        }
    }
}

__global__ void fill_kernel(const int* __restrict__ src, const int* __restrict__ dst,
                            int* __restrict__ cur, int* __restrict__ csr) {
    int e = blockIdx.x * blockDim.x + threadIdx.x;
    if (e < EE) {
        int p = atomicAdd(&cur[dst[e]], 1);
        csr[p] = src[e];
    }
}

// ---------------------------------------------------------------------------
// CSR gather: mean[i] = invdeg_i * sum h[src(e)], emitted as bf16 hi/lo.
// ---------------------------------------------------------------------------
__global__ void gather_kernel(const float* __restrict__ h,
                              const int* __restrict__ csr,
                              const int* __restrict__ off,
                              const int* __restrict__ degi,
                              const float* __restrict__ invdeg,
                              __nv_bfloat16* __restrict__ mhi,
                              __nv_bfloat16* __restrict__ mlo) {
    const int node = blockIdx.x;
    const int t = threadIdx.x;               // 0..63
    const int base = off[node];
    const int n = degi[node];
    const float4* hp = (const float4*)h;
    float4 acc = make_float4(0.f, 0.f, 0.f, 0.f);
    int e = 0;
    for (; e + 4 <= n; e += 4) {
        int s0 = csr[base + e + 0];
        int s1 = csr[base + e + 1];
        int s2 = csr[base + e + 2];
        int s3 = csr[base + e + 3];
        float4 v0 = hp[(size_t)s0 * 64 + t];
        float4 v1 = hp[(size_t)s1 * 64 + t];
        float4 v2 = hp[(size_t)s2 * 64 + t];
        float4 v3 = hp[(size_t)s3 * 64 + t];
        acc.x += (v0.x + v1.x) + (v2.x + v3.x);
        acc.y += (v0.y + v1.y) + (v2.y + v3.y);
        acc.z += (v0.z + v1.z) + (v2.z + v3.z);
        acc.w += (v0.w + v1.w) + (v2.w + v3.w);
    }
    for (; e < n; e++) {
        int s = csr[base + e];
        float4 v = hp[(size_t)s * 64 + t];
        acc.x += v.x; acc.y += v.y; acc.z += v.z; acc.w += v.w;
    }
    const float s = invdeg[node];
    float o[4] = {acc.x * s, acc.y * s, acc.z * s, acc.w * s};
    __nv_bfloat16 hi[4], lo[4];
#pragma unroll
    for (int j = 0; j < 4; j++) {
        hi[j] = __float2bfloat16(o[j]);
        lo[j] = __float2bfloat16(o[j] - __bfloat162float(hi[j]));
    }
    size_t p = (size_t)node * DOUT + t * 4;
    __nv_bfloat162 a, b;
    a.x = hi[0]; a.y = hi[1]; b.x = hi[2]; b.y = hi[3];
    *(__nv_bfloat162*)(mhi + p) = a; *(__nv_bfloat162*)(mhi + p + 2) = b;
    a.x = lo[0]; a.y = lo[1]; b.x = lo[2]; b.y = lo[3];
    *(__nv_bfloat162*)(mlo + p) = a; *(__nv_bfloat162*)(mlo + p + 2) = b;
}

// ---------------------------------------------------------------------------
// Tensor-core GEMM, bf16x3 with MERGED-OPERAND stages: each pipeline stage
// loads the quad (Ahi, Alo, Whi, Wlo) once and issues all 3 split-term MMA
// combinations (Ahi*Whi + Alo*Whi + Ahi*Wlo). 3x fewer stages/barriers,
// 2/3 the smem write traffic, identical math.
// Block 64x64, 4 warps (32x32 warp tile), BK=32, PIPE=3 (57 KB smem).
// ---------------------------------------------------------------------------
#define LDSM4(d0, d1, d2, d3, addr) \
    asm volatile("ldmatrix.sync.aligned.m8n8.x4.shared.b16 {%0,%1,%2,%3}, [%4];" \
        : "=r"(d0), "=r"(d1), "=r"(d2), "=r"(d3) : "r"(addr))
#define LDSM4T(d0, d1, d2, d3, addr) \
    asm volatile("ldmatrix.sync.aligned.m8n8.x4.trans.shared.b16 {%0,%1,%2,%3}, [%4];" \
        : "=r"(d0), "=r"(d1), "=r"(d2), "=r"(d3) : "r"(addr))
#define MMA16816(c, a, b0, b1) \
    asm volatile("mma.sync.aligned.m16n8k16.row.col.f32.bf16.bf16.f32 " \
        "{%0,%1,%2,%3}, {%4,%5,%6,%7}, {%8,%9}, {%0,%1,%2,%3};" \
        : "+f"(c[0]), "+f"(c[1]), "+f"(c[2]), "+f"(c[3]) \
        : "r"(a[0]), "r"(a[1]), "r"(a[2]), "r"(a[3]), "r"(b0), "r"(b1))
#define CPA16(dst, src, sz) \
    asm volatile("cp.async.cg.shared.global [%0], [%1], 16, %2;" \
        :: "r"(dst), "l"(src), "r"(sz))
#define CPA_COMMIT() asm volatile("cp.async.commit_group;")

constexpr int ASTR = 40;           // halfs; 80B row stride (conflict-free ldsm)
constexpr int WSTR = 72;           // halfs; 144B row stride (conflict-free ldsm)
constexpr int ABUF = 64 * ASTR;    // halfs per A tile (64 rows x 32 k)
constexpr int WBUF = 32 * WSTR;    // halfs per W tile (32 k x 64 n)
constexpr int PIPE = 3;

template<int K, bool BIAS, bool ADD, bool RELU, bool RES, bool OUTS>
__global__ __launch_bounds__(128)
void gemm_mma(const __nv_bfloat16* __restrict__ Ahi, const __nv_bfloat16* __restrict__ Alo,
              const __nv_bfloat16* __restrict__ Whi, const __nv_bfloat16* __restrict__ Wlo,
              const float* __restrict__ bias, const float* __restrict__ add,
              const float* __restrict__ res,
              float* __restrict__ C, __nv_bfloat16* __restrict__ Chi,
              __nv_bfloat16* __restrict__ Clo, int M) {
    constexpr int NST = K / 32;        // merged stages (16 for K=512, 8 for K=256)
    __shared__ __align__(16) __nv_bfloat16 As[PIPE * 2 * ABUF];   // [pipe][hi/lo]
    __shared__ __align__(16) __nv_bfloat16 Ws[PIPE * 2 * WBUF];   // [pipe][hi/lo]

    const int tid = threadIdx.x, wid = tid >> 5, lane = tid & 31;
    const int row0 = blockIdx.y * 64, col0 = blockIdx.x * 64;
    const int mb = (wid & 1) * 32, nb = (wid >> 1) * 32;

    float acc[2][4][4];
#pragma unroll
    for (int mt = 0; mt < 2; mt++)
#pragma unroll
        for (int nt = 0; nt < 4; nt++)
#pragma unroll
            for (int r = 0; r < 4; r++) acc[mt][nt][r] = 0.f;

    // cp.async mapping (128 threads); per stage: 4 A chunks + 4 W chunks.
    const int arow = tid >> 2;
    const int achunk = (tid & 3) * 8;
    const int wk = tid >> 2;
    const int wn = (tid & 3) * 16;

    const uint32_t asu = (uint32_t)__cvta_generic_to_shared(As);
    const uint32_t wsu = (uint32_t)__cvta_generic_to_shared(Ws);

    const int r0g = row0 + arow, r1g = r0g + 32;
    const int sz0 = (r0g < M) ? 16 : 0, sz1 = (r1g < M) ? 16 : 0;
    const int r0c = (r0g < M) ? r0g : 0, r1c = (r1g < M) ? r1g : 0;

#define ISSUE(S, BUF) { \
        const int k0 = (S) * 32; \
        const uint32_t ah = asu + ((BUF) * 2 * ABUF) * 2; \
        const uint32_t al = ah + ABUF * 2; \
        const uint32_t wh = wsu + ((BUF) * 2 * WBUF) * 2; \
        const uint32_t wl = wh + WBUF * 2; \
        CPA16(ah + (arow * ASTR + achunk) * 2,        Ahi + (size_t)r0c * K + k0 + achunk, sz0); \
        CPA16(ah + ((arow + 32) * ASTR + achunk) * 2, Ahi + (size_t)r1c * K + k0 + achunk, sz1); \
        CPA16(al + (arow * ASTR + achunk) * 2,        Alo + (size_t)r0c * K + k0 + achunk, sz0); \
        CPA16(al + ((arow + 32) * ASTR + achunk) * 2, Alo + (size_t)r1c * K + k0 + achunk, sz1); \
        CPA16(wh + (wk * WSTR + wn) * 2,              Whi + (size_t)(k0 + wk) * DOUT + col0 + wn, 16); \
        CPA16(wh + (wk * WSTR + wn + 8) * 2,          Whi + (size_t)(k0 + wk) * DOUT + col0 + wn + 8, 16); \
        CPA16(wl + (wk * WSTR + wn) * 2,              Wlo + (size_t)(k0 + wk) * DOUT + col0 + wn, 16); \
        CPA16(wl + (wk * WSTR + wn + 8) * 2,          Wlo + (size_t)(k0 + wk) * DOUT + col0 + wn + 8, 16); \
        CPA_COMMIT(); \
    }

    ISSUE(0, 0);
    if (NST > 1) ISSUE(1, 1);

    const int r = lane & 7, selr = lane >> 3;
    const uint32_t aoff = (uint32_t)((mb + (selr & 1) * 8 + r) * ASTR + (selr >> 1) * 8) * 2;
    const uint32_t boff = (uint32_t)(((selr & 1) * 8 + r) * WSTR + nb + (selr >> 1) * 8) * 2;

    for (int s = 0; s < NST; s++) {
        if (s + 1 < NST) { asm volatile("cp.async.wait_group 1;"); }
        else             { asm volatile("cp.async.wait_group 0;"); }
        __syncthreads();
        // Safe: buffer (s+2)%3 == (s-1)%3, whose readers all passed this barrier.
        if (s + 2 < NST) ISSUE(s + 2, (s + 2) % PIPE);

        const int buf = s % PIPE;
        const uint32_t ahb = asu + (buf * 2 * ABUF) * 2 + aoff;
        const uint32_t alb = ahb + ABUF * 2;
        const uint32_t whb = wsu + (buf * 2 * WBUF) * 2 + boff;
        const uint32_t wlb = whb + WBUF * 2;
#pragma unroll
        for (int kk = 0; kk < 32; kk += 16) {
            uint32_t ahr[2][4], alr[2][4], bh0[4], bh1[4], bl0[4], bl1[4];
            LDSM4(ahr[0][0], ahr[0][1], ahr[0][2], ahr[0][3], ahb + kk * 2);
            LDSM4(ahr[1][0], ahr[1][1], ahr[1][2], ahr[1][3], ahb + kk * 2 + 16 * ASTR * 2);
            LDSM4(alr[0][0], alr[0][1], alr[0][2], alr[0][3], alb + kk * 2);
            LDSM4(alr[1][0], alr[1][1], alr[1][2], alr[1][3], alb + kk * 2 + 16 * ASTR * 2);
            const uint32_t bhk = whb + kk * WSTR * 2;
            const uint32_t blk = wlb + kk * WSTR * 2;
            LDSM4T(bh0[0], bh0[1], bh0[2], bh0[3], bhk);
            LDSM4T(bh1[0], bh1[1], bh1[2], bh1[3], bhk + 16 * 2);
            LDSM4T(bl0[0], bl0[1], bl0[2], bl0[3], blk);
            LDSM4T(bl1[0], bl1[1], bl1[2], bl1[3], blk + 16 * 2);
#pragma unroll
            for (int mt = 0; mt < 2; mt++) {
                // Ahi * Whi
                MMA16816(acc[mt][0], ahr[mt], bh0[0], bh0[1]);
                MMA16816(acc[mt][1], ahr[mt], bh0[2], bh0[3]);
                MMA16816(acc[mt][2], ahr[mt], bh1[0], bh1[1]);
                MMA16816(acc[mt][3], ahr[mt], bh1[2], bh1[3]);
                // Alo * Whi
                MMA16816(acc[mt][0], alr[mt], bh0[0], bh0[1]);
                MMA16816(acc[mt][1], alr[mt], bh0[2], bh0[3]);
                MMA16816(acc[mt][2], alr[mt], bh1[0], bh1[1]);
                MMA16816(acc[mt][3], alr[mt], bh1[2], bh1[3]);
                // Ahi * Wlo
                MMA16816(acc[mt][0], ahr[mt], bl0[0], bl0[1]);
                MMA16816(acc[mt][1], ahr[mt], bl0[2], bl0[3]);
                MMA16816(acc[mt][2], ahr[mt], bl1[0], bl1[1]);
                MMA16816(acc[mt][3], ahr[mt], bl1[2], bl1[3]);
            }
        }
    }
#undef ISSUE

    // epilogue: [+bias] [+add] [relu] [+res]
    const int g = lane >> 2, tig = lane & 3;
#pragma unroll
    for (int mt = 0; mt < 2; mt++) {
#pragma unroll
        for (int half = 0; half < 2; half++) {
            const int row = row0 + mb + mt * 16 + g + half * 8;
            if (row >= M) continue;
#pragma unroll
            for (int nt = 0; nt < 4; nt++) {
                const int col = col0 + nb + nt * 8 + tig * 2;
                float v0 = acc[mt][nt][half * 2 + 0];
                float v1 = acc[mt][nt][half * 2 + 1];
                if (BIAS) { v0 += bias[col]; v1 += bias[col + 1]; }
                if (ADD) {
                    float2 aa = *(const float2*)(add + (size_t)row * DOUT + col);
                    v0 += aa.x; v1 += aa.y;
                }
                if (RELU) { v0 = fmaxf(v0, 0.f); v1 = fmaxf(v1, 0.f); }
                if (RES) {
                    float2 rr = *(const float2*)(res + (size_t)row * DOUT + col);
                    v0 += rr.x; v1 += rr.y;
                }
                float2 o; o.x = v0; o.y = v1;
                *(float2*)(C + (size_t)row * DOUT + col) = o;
                if (OUTS) {
                    __nv_bfloat16 h0 = __float2bfloat16(v0), h1 = __float2bfloat16(v1);
                    __nv_bfloat162 hh; hh.x = h0; hh.y = h1;
                    *(__nv_bfloat162*)(Chi + (size_t)row * DOUT + col) = hh;
                    __nv_bfloat162 ll;
                    ll.x = __float2bfloat16(v0 - __bfloat162float(h0));
                    ll.y = __float2bfloat16(v1 - __bfloat162float(h1));
                    *(__nv_bfloat162*)(Clo + (size_t)row * DOUT + col) = ll;
                }
            }
        }
    }
}

// ---------------------------------------------------------------------------
// Launch graph (dual-stream, as R13):
//   main: detect decode | split gemm1 | tmp1=h@Wr1 | gemm2b | tmp2=o1@Wr2 | gemm3b
//   s2:             \-> scan fill      \-> gather1 -/   \-> gather2 -/
// ---------------------------------------------------------------------------
extern "C" void kernel_launch(void* const* d_in, const int* in_sizes, int n_in,
                              void* d_out, int out_size) {
    const float* x   = (const float*)d_in[0];
    const int*   ei  = (const int*)d_in[1];
    const float* W0  = (const float*)d_in[2];
    const float* b0  = (const float*)d_in[3];
    const float* Wl1 = (const float*)d_in[4];
    const float* bl1 = (const float*)d_in[5];
    const float* Wr1 = (const float*)d_in[6];
    const float* Wl2 = (const float*)d_in[7];
    const float* bl2 = (const float*)d_in[8];
    const float* Wr2 = (const float*)d_in[9];

    float* out1 = (float*)d_out;
    float* out2 = out1 + (size_t)NN * DOUT;

    float *h, *tmp, *invdeg;
    int *degi, *off, *cur, *src, *dst, *csr;
    __nv_bfloat16 *xhi, *xlo, *w0hi, *w0lo, *wl1hi, *wl1lo, *wr1hi, *wr1lo;
    __nv_bfloat16 *wl2hi, *wl2lo, *wr2hi, *wr2lo, *hhi, *hlo, *mhi, *mlo, *o1hi, *o1lo;
    cudaGetSymbolAddress((void**)&h,      g_h);
    cudaGetSymbolAddress((void**)&tmp,    g_tmp);
    cudaGetSymbolAddress((void**)&invdeg, g_invdeg);
    cudaGetSymbolAddress((void**)&degi,   g_degi);
    cudaGetSymbolAddress((void**)&off,    g_off);
    cudaGetSymbolAddress((void**)&cur,    g_cur);
    cudaGetSymbolAddress((void**)&src,    g_src);
    cudaGetSymbolAddress((void**)&dst,    g_dst);
    cudaGetSymbolAddress((void**)&csr,    g_csr);
    cudaGetSymbolAddress((void**)&xhi,   g_xhi);   cudaGetSymbolAddress((void**)&xlo,   g_xlo);
    cudaGetSymbolAddress((void**)&w0hi,  g_w0hi);  cudaGetSymbolAddress((void**)&w0lo,  g_w0lo);
    cudaGetSymbolAddress((void**)&wl1hi, g_wl1hi); cudaGetSymbolAddress((void**)&wl1lo, g_wl1lo);
    cudaGetSymbolAddress((void**)&wr1hi, g_wr1hi); cudaGetSymbolAddress((void**)&wr1lo, g_wr1lo);
    cudaGetSymbolAddress((void**)&wl2hi, g_wl2hi); cudaGetSymbolAddress((void**)&wl2lo, g_wl2lo);
    cudaGetSymbolAddress((void**)&wr2hi, g_wr2hi); cudaGetSymbolAddress((void**)&wr2lo, g_wr2lo);
    cudaGetSymbolAddress((void**)&hhi,   g_hhi);   cudaGetSymbolAddress((void**)&hlo,   g_hlo);
    cudaGetSymbolAddress((void**)&mhi,   g_mhi);   cudaGetSymbolAddress((void**)&mlo,   g_mlo);
    cudaGetSymbolAddress((void**)&o1hi,  g_o1hi);  cudaGetSymbolAddress((void**)&o1lo,  g_o1lo);

    // Static side stream + events (created on first, uncaptured call).
    static cudaStream_t s2 = nullptr;
    static cudaEvent_t eA = nullptr, eH = nullptr, eG1 = nullptr, eO1 = nullptr, eG2 = nullptr;
    if (!s2) {
        cudaStreamCreateWithFlags(&s2, cudaStreamNonBlocking);
        cudaEventCreateWithFlags(&eA,  cudaEventDisableTiming);
        cudaEventCreateWithFlags(&eH,  cudaEventDisableTiming);
        cudaEventCreateWithFlags(&eG1, cudaEventDisableTiming);
        cudaEventCreateWithFlags(&eO1, cudaEventDisableTiming);
        cudaEventCreateWithFlags(&eG2, cudaEventDisableTiming);
    }

    const int EB = (EE + 255) / 256;
    const int SPLIT_N = NN * DIN + DIN * DOUT + 4 * DOUT * DOUT;
    dim3 mgrid(DOUT / 64, (NN + 63) / 64);    // (4, 157) = 628 blocks

    // main: edge decode
    detect_kernel<<<1, 256>>>(ei);
    cudaMemsetAsync(degi, 0, NN * sizeof(int));
    decode_degi_kernel<<<EB, 256>>>(ei, src, dst, degi);
    cudaEventRecord(eA, 0);

    // s2: CSR build (overlaps split + gemm1)
    cudaStreamWaitEvent(s2, eA, 0);
    scan_kernel<<<1, 256, 0, s2>>>(degi, off, cur, invdeg);
    fill_kernel<<<EB, 256, 0, s2>>>(src, dst, cur, csr);

    // main: split + gemm1 (h = x@W0 + b0)
    split_kernel<<<(SPLIT_N + 255) / 256, 256>>>(x, W0, Wl1, Wr1, Wl2, Wr2);
    gemm_mma<DIN, true, false, false, false, true><<<mgrid, 128>>>(
        xhi, xlo, w0hi, w0lo, b0, nullptr, nullptr, h, hhi, hlo, NN);
    cudaEventRecord(eH, 0);

    // s2: gather1 (needs h + CSR) || main: tmp1 = h@Wr1
    cudaStreamWaitEvent(s2, eH, 0);
    gather_kernel<<<NN, 64, 0, s2>>>(h, csr, off, degi, invdeg, mhi, mlo);
    cudaEventRecord(eG1, s2);
    gemm_mma<DOUT, false, false, false, false, false><<<mgrid, 128>>>(
        hhi, hlo, wr1hi, wr1lo, nullptr, nullptr, nullptr, tmp, nullptr, nullptr, NN);

    // main: out1 = relu(mean@Wl1 + bl1 + tmp1) + h
    cudaStreamWaitEvent(0, eG1, 0);
    gemm_mma<DOUT, true, true, true, true, true><<<mgrid, 128>>>(
        mhi, mlo, wl1hi, wl1lo, bl1, tmp, h, out1, o1hi, o1lo, NN);
    cudaEventRecord(eO1, 0);

    // s2: gather2 (needs out1 + CSR) || main: tmp2 = out1@Wr2
    cudaStreamWaitEvent(s2, eO1, 0);
    gather_kernel<<<NN, 64, 0, s2>>>(out1, csr, off, degi, invdeg, mhi, mlo);
    cudaEventRecord(eG2, s2);
    gemm_mma<DOUT, false, false, false, false, false><<<mgrid, 128>>>(
        o1hi, o1lo, wr2hi, wr2lo, nullptr, nullptr, nullptr, tmp, nullptr, nullptr, NN);

    // main: out2 = mean@Wl2 + bl2 + tmp2 + out1
    cudaStreamWaitEvent(0, eG2, 0);
    gemm_mma<DOUT, true, true, false, true, false><<<mgrid, 128>>>(
        mhi, mlo, wl2hi, wl2lo, bl2, tmp, out1, out2, nullptr, nullptr, NN);
}

// round 16
// speedup vs baseline: 1.5608x; 1.0573x over previous
#include <cuda_runtime.h>
#include <cuda_bf16.h>
#include <cstdint>
#include <cstddef>

constexpr int NN   = 10000;
constexpr int EE   = 320000;
constexpr int DIN  = 512;
constexpr int DOUT = 256;

// Row chunking for gather/combine overlap (chunk0 multiple of 64)
constexpr int CH0 = 5056;             // 79 GEMM row-blocks of 64
constexpr int CH1 = NN - CH0;         // 4944 -> 78 row-blocks (last partial)

// ---------------- scratch (__device__ globals; no allocs allowed) ----------
__device__ float g_h[(size_t)NN * DOUT];
__device__ float g_tmp[(size_t)NN * DOUT];
__device__ float g_invdeg[NN];
__device__ int   g_degi[NN];
__device__ int   g_off[NN];
__device__ int   g_cur[NN];
__device__ int   g_src[EE];
__device__ int   g_dst[EE];
__device__ int   g_csr[EE];
__device__ int   g_is64;

// bf16 hi/lo split operands (weights in natural [K][N] layout)
__device__ __nv_bfloat16 g_xhi[(size_t)NN * DIN],  g_xlo[(size_t)NN * DIN];
__device__ __nv_bfloat16 g_w0hi[DIN * DOUT],       g_w0lo[DIN * DOUT];
__device__ __nv_bfloat16 g_wl1hi[DOUT * DOUT],     g_wl1lo[DOUT * DOUT];
__device__ __nv_bfloat16 g_wr1hi[DOUT * DOUT],     g_wr1lo[DOUT * DOUT];
__device__ __nv_bfloat16 g_wl2hi[DOUT * DOUT],     g_wl2lo[DOUT * DOUT];
__device__ __nv_bfloat16 g_wr2hi[DOUT * DOUT],     g_wr2lo[DOUT * DOUT];
__device__ __nv_bfloat16 g_hhi[(size_t)NN * DOUT], g_hlo[(size_t)NN * DOUT];
__device__ __nv_bfloat16 g_mhi[(size_t)NN * DOUT], g_mlo[(size_t)NN * DOUT];
__device__ __nv_bfloat16 g_o1hi[(size_t)NN * DOUT], g_o1lo[(size_t)NN * DOUT];

// ---------------------------------------------------------------------------
// Edge-index dtype detection (int64 vs int32).
// ---------------------------------------------------------------------------
__global__ void detect_kernel(const int* __restrict__ raw) {
    int nz = 0;
    for (int i = threadIdx.x; i < 1024; i += blockDim.x)
        nz |= (raw[2 * i + 1] != 0);
    nz = __syncthreads_or(nz);
    if (threadIdx.x == 0) g_is64 = nz ? 0 : 1;
}

// Decode edge_index into int32 src/dst + in-degree histogram.
__global__ void decode_degi_kernel(const int* __restrict__ raw,
                                   int* __restrict__ src, int* __restrict__ dst,
                                   int* __restrict__ degi) {
    int e = blockIdx.x * blockDim.x + threadIdx.x;
    if (e >= EE) return;
    int s, d;
    if (g_is64) { s = raw[2 * e]; d = raw[2 * (EE + e)]; }
    else        { s = raw[e];     d = raw[EE + e]; }
    src[e] = s;
    dst[e] = d;
    atomicAdd(&degi[d], 1);
}

// ---------------------------------------------------------------------------
// bf16 hi/lo split of x and the five weight matrices (one launch).
// ---------------------------------------------------------------------------
__global__ void split_kernel(const float* __restrict__ x,  const float* __restrict__ W0,
                             const float* __restrict__ Wl1, const float* __restrict__ Wr1,
                             const float* __restrict__ Wl2, const float* __restrict__ Wr2) {
    constexpr int S0 = NN * DIN;
    constexpr int S1 = DIN * DOUT;
    constexpr int S2 = DOUT * DOUT;
    int i = blockIdx.x * blockDim.x + threadIdx.x;
    const float* src; __nv_bfloat16 *hi, *lo; int off;
    if      (i < S0)               { src = x;   hi = g_xhi;  lo = g_xlo;  off = i; }
    else if (i < S0 + S1)          { src = W0;  hi = g_w0hi; lo = g_w0lo; off = i - S0; }
    else if (i < S0 + S1 + S2)     { src = Wl1; hi = g_wl1hi; lo = g_wl1lo; off = i - S0 - S1; }
    else if (i < S0 + S1 + 2 * S2) { src = Wr1; hi = g_wr1hi; lo = g_wr1lo; off = i - S0 - S1 - S2; }
    else if (i < S0 + S1 + 3 * S2) { src = Wl2; hi = g_wl2hi; lo = g_wl2lo; off = i - S0 - S1 - 2 * S2; }
    else if (i < S0 + S1 + 4 * S2) { src = Wr2; hi = g_wr2hi; lo = g_wr2lo; off = i - S0 - S1 - 3 * S2; }
    else return;
    float v = src[off];
    __nv_bfloat16 h = __float2bfloat16(v);
    hi[off] = h;
    lo[off] = __float2bfloat16(v - __bfloat162float(h));
}

// ---------------------------------------------------------------------------
// Exclusive scan over degrees -> CSR offsets + cursors + invdeg (1 block).
// ---------------------------------------------------------------------------
__global__ void scan_kernel(const int* __restrict__ degi, int* __restrict__ off,
                            int* __restrict__ cur, float* __restrict__ invdeg) {
    __shared__ int part[256];
    const int t = threadIdx.x;
    const int CH = (NN + 255) / 256;
    const int s0 = t * CH;
    int sum = 0;
    for (int j = 0; j < CH; j++) { int i = s0 + j; if (i < NN) sum += degi[i]; }
    part[t] = sum;
    __syncthreads();
    for (int d = 1; d < 256; d <<= 1) {
        int v = (t >= d) ? part[t - d] : 0;
        __syncthreads();
        part[t] += v;
        __syncthreads();
    }
    int run = (t > 0) ? part[t - 1] : 0;
    for (int j = 0; j < CH; j++) {
        int i = s0 + j;
        if (i < NN) {
            off[i] = run; cur[i] = run;
            int d = degi[i]; run += d;
            invdeg[i] = 1.0f / fmaxf((float)d, 1.0f);
        }
    }
}

__global__ void fill_kernel(const int* __restrict__ src, const int* __restrict__ dst,
                            int* __restrict__ cur, int* __restrict__ csr) {
    int e = blockIdx.x * blockDim.x + threadIdx.x;
    if (e < EE) {
        int p = atomicAdd(&cur[dst[e]], 1);
        csr[p] = src[e];
    }
}

// ---------------------------------------------------------------------------
// CSR gather for node range [base, base+gridDim.x): one block per node.
// ---------------------------------------------------------------------------
__global__ void gather_kernel(const float* __restrict__ h,
                              const int* __restrict__ csr,
                              const int* __restrict__ off,
                              const int* __restrict__ degi,
                              const float* __restrict__ invdeg,
                              __nv_bfloat16* __restrict__ mhi,
                              __nv_bfloat16* __restrict__ mlo,
                              int base) {
    const int node = base + blockIdx.x;
    const int t = threadIdx.x;               // 0..63
    const int eb = off[node];
    const int n = degi[node];
    const float4* hp = (const float4*)h;
    float4 acc = make_float4(0.f, 0.f, 0.f, 0.f);
    int e = 0;
    for (; e + 4 <= n; e += 4) {
        int s0 = csr[eb + e + 0];
        int s1 = csr[eb + e + 1];
        int s2 = csr[eb + e + 2];
        int s3 = csr[eb + e + 3];
        float4 v0 = hp[(size_t)s0 * 64 + t];
        float4 v1 = hp[(size_t)s1 * 64 + t];
        float4 v2 = hp[(size_t)s2 * 64 + t];
        float4 v3 = hp[(size_t)s3 * 64 + t];
        acc.x += (v0.x + v1.x) + (v2.x + v3.x);
        acc.y += (v0.y + v1.y) + (v2.y + v3.y);
        acc.z += (v0.z + v1.z) + (v2.z + v3.z);
        acc.w += (v0.w + v1.w) + (v2.w + v3.w);
    }
    for (; e < n; e++) {
        int s = csr[eb + e];
        float4 v = hp[(size_t)s * 64 + t];
        acc.x += v.x; acc.y += v.y; acc.z += v.z; acc.w += v.w;
    }
    const float s = invdeg[node];
    float o[4] = {acc.x * s, acc.y * s, acc.z * s, acc.w * s};
    __nv_bfloat16 hi[4], lo[4];
#pragma unroll
    for (int j = 0; j < 4; j++) {
        hi[j] = __float2bfloat16(o[j]);
        lo[j] = __float2bfloat16(o[j] - __bfloat162float(hi[j]));
    }
    size_t p = (size_t)node * DOUT + t * 4;
    __nv_bfloat162 a, b;
    a.x = hi[0]; a.y = hi[1]; b.x = hi[2]; b.y = hi[3];
    *(__nv_bfloat162*)(mhi + p) = a; *(__nv_bfloat162*)(mhi + p + 2) = b;
    a.x = lo[0]; a.y = lo[1]; b.x = lo[2]; b.y = lo[3];
    *(__nv_bfloat162*)(mlo + p) = a; *(__nv_bfloat162*)(mlo + p + 2) = b;
}

// ---------------------------------------------------------------------------
// Tensor-core GEMM, bf16x3 with merged-operand stages (R14 core, unchanged).
// Block 64x64, 4 warps, BK=32, PIPE=3 (57 KB smem).
// ---------------------------------------------------------------------------
#define LDSM4(d0, d1, d2, d3, addr) \
    asm volatile("ldmatrix.sync.aligned.m8n8.x4.shared.b16 {%0,%1,%2,%3}, [%4];" \
        : "=r"(d0), "=r"(d1), "=r"(d2), "=r"(d3) : "r"(addr))
#define LDSM4T(d0, d1, d2, d3, addr) \
    asm volatile("ldmatrix.sync.aligned.m8n8.x4.trans.shared.b16 {%0,%1,%2,%3}, [%4];" \
        : "=r"(d0), "=r"(d1), "=r"(d2), "=r"(d3) : "r"(addr))
#define MMA16816(c, a, b0, b1) \
    asm volatile("mma.sync.aligned.m16n8k16.row.col.f32.bf16.bf16.f32 " \
        "{%0,%1,%2,%3}, {%4,%5,%6,%7}, {%8,%9}, {%0,%1,%2,%3};" \
        : "+f"(c[0]), "+f"(c[1]), "+f"(c[2]), "+f"(c[3]) \
        : "r"(a[0]), "r"(a[1]), "r"(a[2]), "r"(a[3]), "r"(b0), "r"(b1))
#define CPA16(dst, src, sz) \
    asm volatile("cp.async.cg.shared.global [%0], [%1], 16, %2;" \
        :: "r"(dst), "l"(src), "r"(sz))
#define CPA_COMMIT() asm volatile("cp.async.commit_group;")

constexpr int ASTR = 40;           // halfs; 80B row stride (conflict-free ldsm)
constexpr int WSTR = 72;           // halfs; 144B row stride (conflict-free ldsm)
constexpr int ABUF = 64 * ASTR;
constexpr int WBUF = 32 * WSTR;
constexpr int PIPE = 3;

template<int K, bool BIAS, bool ADD, bool RELU, bool RES, bool OUTS>
__global__ __launch_bounds__(128)
void gemm_mma(const __nv_bfloat16* __restrict__ Ahi, const __nv_bfloat16* __restrict__ Alo,
              const __nv_bfloat16* __restrict__ Whi, const __nv_bfloat16* __restrict__ Wlo,
              const float* __restrict__ bias, const float* __restrict__ add,
              const float* __restrict__ res,
              float* __restrict__ C, __nv_bfloat16* __restrict__ Chi,
              __nv_bfloat16* __restrict__ Clo, int M) {
    constexpr int NST = K / 32;
    __shared__ __align__(16) __nv_bfloat16 As[PIPE * 2 * ABUF];
    __shared__ __align__(16) __nv_bfloat16 Ws[PIPE * 2 * WBUF];

    const int tid = threadIdx.x, wid = tid >> 5, lane = tid & 31;
    const int row0 = blockIdx.y * 64, col0 = blockIdx.x * 64;
    const int mb = (wid & 1) * 32, nb = (wid >> 1) * 32;

    float acc[2][4][4];
#pragma unroll
    for (int mt = 0; mt < 2; mt++)
#pragma unroll
        for (int nt = 0; nt < 4; nt++)
#pragma unroll
            for (int r = 0; r < 4; r++) acc[mt][nt][r] = 0.f;

    const int arow = tid >> 2;
    const int achunk = (tid & 3) * 8;
    const int wk = tid >> 2;
    const int wn = (tid & 3) * 16;

    const uint32_t asu = (uint32_t)__cvta_generic_to_shared(As);
    const uint32_t wsu = (uint32_t)__cvta_generic_to_shared(Ws);

    const int r0g = row0 + arow, r1g = r0g + 32;
    const int sz0 = (r0g < M) ? 16 : 0, sz1 = (r1g < M) ? 16 : 0;
    const int r0c = (r0g < M) ? r0g : 0, r1c = (r1g < M) ? r1g : 0;

#define ISSUE(S, BUF) { \
        const int k0 = (S) * 32; \
        const uint32_t ah = asu + ((BUF) * 2 * ABUF) * 2; \
        const uint32_t al = ah + ABUF * 2; \
        const uint32_t wh = wsu + ((BUF) * 2 * WBUF) * 2; \
        const uint32_t wl = wh + WBUF * 2; \
        CPA16(ah + (arow * ASTR + achunk) * 2,        Ahi + (size_t)r0c * K + k0 + achunk, sz0); \
        CPA16(ah + ((arow + 32) * ASTR + achunk) * 2, Ahi + (size_t)r1c * K + k0 + achunk, sz1); \
        CPA16(al + (arow * ASTR + achunk) * 2,        Alo + (size_t)r0c * K + k0 + achunk, sz0); \
        CPA16(al + ((arow + 32) * ASTR + achunk) * 2, Alo + (size_t)r1c * K + k0 + achunk, sz1); \
        CPA16(wh + (wk * WSTR + wn) * 2,              Whi + (size_t)(k0 + wk) * DOUT + col0 + wn, 16); \
        CPA16(wh + (wk * WSTR + wn + 8) * 2,          Whi + (size_t)(k0 + wk) * DOUT + col0 + wn + 8, 16); \
        CPA16(wl + (wk * WSTR + wn) * 2,              Wlo + (size_t)(k0 + wk) * DOUT + col0 + wn, 16); \
        CPA16(wl + (wk * WSTR + wn + 8) * 2,          Wlo + (size_t)(k0 + wk) * DOUT + col0 + wn + 8, 16); \
        CPA_COMMIT(); \
    }

    ISSUE(0, 0);
    if (NST > 1) ISSUE(1, 1);

    const int r = lane & 7, selr = lane >> 3;
    const uint32_t aoff = (uint32_t)((mb + (selr & 1) * 8 + r) * ASTR + (selr >> 1) * 8) * 2;
    const uint32_t boff = (uint32_t)(((selr & 1) * 8 + r) * WSTR + nb + (selr >> 1) * 8) * 2;

    for (int s = 0; s < NST; s++) {
        if (s + 1 < NST) { asm volatile("cp.async.wait_group 1;"); }
        else             { asm volatile("cp.async.wait_group 0;"); }
        __syncthreads();
        if (s + 2 < NST) ISSUE(s + 2, (s + 2) % PIPE);

        const int buf = s % PIPE;
        const uint32_t ahb = asu + (buf * 2 * ABUF) * 2 + aoff;
        const uint32_t alb = ahb + ABUF * 2;
        const uint32_t whb = wsu + (buf * 2 * WBUF) * 2 + boff;
        const uint32_t wlb = whb + WBUF * 2;
#pragma unroll
        for (int kk = 0; kk < 32; kk += 16) {
            uint32_t ahr[2][4], alr[2][4], bh0[4], bh1[4], bl0[4], bl1[4];
            LDSM4(ahr[0][0], ahr[0][1], ahr[0][2], ahr[0][3], ahb + kk * 2);
            LDSM4(ahr[1][0], ahr[1][1], ahr[1][2], ahr[1][3], ahb + kk * 2 + 16 * ASTR * 2);
            LDSM4(alr[0][0], alr[0][1], alr[0][2], alr[0][3], alb + kk * 2);
            LDSM4(alr[1][0], alr[1][1], alr[1][2], alr[1][3], alb + kk * 2 + 16 * ASTR * 2);
            const uint32_t bhk = whb + kk * WSTR * 2;
            const uint32_t blk = wlb + kk * WSTR * 2;
            LDSM4T(bh0[0], bh0[1], bh0[2], bh0[3], bhk);
            LDSM4T(bh1[0], bh1[1], bh1[2], bh1[3], bhk + 16 * 2);
            LDSM4T(bl0[0], bl0[1], bl0[2], bl0[3], blk);
            LDSM4T(bl1[0], bl1[1], bl1[2], bl1[3], blk + 16 * 2);
#pragma unroll
            for (int mt = 0; mt < 2; mt++) {
                MMA16816(acc[mt][0], ahr[mt], bh0[0], bh0[1]);
                MMA16816(acc[mt][1], ahr[mt], bh0[2], bh0[3]);
                MMA16816(acc[mt][2], ahr[mt], bh1[0], bh1[1]);
                MMA16816(acc[mt][3], ahr[mt], bh1[2], bh1[3]);
                MMA16816(acc[mt][0], alr[mt], bh0[0], bh0[1]);
                MMA16816(acc[mt][1], alr[mt], bh0[2], bh0[3]);
                MMA16816(acc[mt][2], alr[mt], bh1[0], bh1[1]);
                MMA16816(acc[mt][3], alr[mt], bh1[2], bh1[3]);
                MMA16816(acc[mt][0], ahr[mt], bl0[0], bl0[1]);
                MMA16816(acc[mt][1], ahr[mt], bl0[2], bl0[3]);
                MMA16816(acc[mt][2], ahr[mt], bl1[0], bl1[1]);
                MMA16816(acc[mt][3], ahr[mt], bl1[2], bl1[3]);
            }
        }
    }
#undef ISSUE

    // epilogue: [+bias] [+add] [relu] [+res]
    const int g = lane >> 2, tig = lane & 3;
#pragma unroll
    for (int mt = 0; mt < 2; mt++) {
#pragma unroll
        for (int half = 0; half < 2; half++) {
            const int row = row0 + mb + mt * 16 + g + half * 8;
            if (row >= M) continue;
#pragma unroll
            for (int nt = 0; nt < 4; nt++) {
                const int col = col0 + nb + nt * 8 + tig * 2;
                float v0 = acc[mt][nt][half * 2 + 0];
                float v1 = acc[mt][nt][half * 2 + 1];
                if (BIAS) { v0 += bias[col]; v1 += bias[col + 1]; }
                if (ADD) {
                    float2 aa = *(const float2*)(add + (size_t)row * DOUT + col);
                    v0 += aa.x; v1 += aa.y;
                }
                if (RELU) { v0 = fmaxf(v0, 0.f); v1 = fmaxf(v1, 0.f); }
                if (RES) {
                    float2 rr = *(const float2*)(res + (size_t)row * DOUT + col);
                    v0 += rr.x; v1 += rr.y;
                }
                float2 o; o.x = v0; o.y = v1;
                *(float2*)(C + (size_t)row * DOUT + col) = o;
                if (OUTS) {
                    __nv_bfloat16 h0 = __float2bfloat16(v0), h1 = __float2bfloat16(v1);
                    __nv_bfloat162 hh; hh.x = h0; hh.y = h1;
                    *(__nv_bfloat162*)(Chi + (size_t)row * DOUT + col) = hh;
                    __nv_bfloat162 ll;
                    ll.x = __float2bfloat16(v0 - __bfloat162float(h0));
                    ll.y = __float2bfloat16(v1 - __bfloat162float(h1));
                    *(__nv_bfloat162*)(Clo + (size_t)row * DOUT + col) = ll;
                }
            }
        }
    }
}

// ---------------------------------------------------------------------------
// Launch graph (dual-stream, chunked gather/combine):
//   main: split gemm1 | tmp1 c1a c1b | tmp2 c2a c2b
//   s2:   detect decode scan fill | gather1a gather1b | gather2a gather2b
// ---------------------------------------------------------------------------
extern "C" void kernel_launch(void* const* d_in, const int* in_sizes, int n_in,
                              void* d_out, int out_size) {
    const float* x   = (const float*)d_in[0];
    const int*   ei  = (const int*)d_in[1];
    const float* W0  = (const float*)d_in[2];
    const float* b0  = (const float*)d_in[3];
    const float* Wl1 = (const float*)d_in[4];
    const float* bl1 = (const float*)d_in[5];
    const float* Wr1 = (const float*)d_in[6];
    const float* Wl2 = (const float*)d_in[7];
    const float* bl2 = (const float*)d_in[8];
    const float* Wr2 = (const float*)d_in[9];

    float* out1 = (float*)d_out;
    float* out2 = out1 + (size_t)NN * DOUT;

    float *h, *tmp, *invdeg;
    int *degi, *off, *cur, *src, *dst, *csr;
    __nv_bfloat16 *xhi, *xlo, *w0hi, *w0lo, *wl1hi, *wl1lo, *wr1hi, *wr1lo;
    __nv_bfloat16 *wl2hi, *wl2lo, *wr2hi, *wr2lo, *hhi, *hlo, *mhi, *mlo, *o1hi, *o1lo;
    cudaGetSymbolAddress((void**)&h,      g_h);
    cudaGetSymbolAddress((void**)&tmp,    g_tmp);
    cudaGetSymbolAddress((void**)&invdeg, g_invdeg);
    cudaGetSymbolAddress((void**)&degi,   g_degi);
    cudaGetSymbolAddress((void**)&off,    g_off);
    cudaGetSymbolAddress((void**)&cur,    g_cur);
    cudaGetSymbolAddress((void**)&src,    g_src);
    cudaGetSymbolAddress((void**)&dst,    g_dst);
    cudaGetSymbolAddress((void**)&csr,    g_csr);
    cudaGetSymbolAddress((void**)&xhi,   g_xhi);   cudaGetSymbolAddress((void**)&xlo,   g_xlo);
    cudaGetSymbolAddress((void**)&w0hi,  g_w0hi);  cudaGetSymbolAddress((void**)&w0lo,  g_w0lo);
    cudaGetSymbolAddress((void**)&wl1hi, g_wl1hi); cudaGetSymbolAddress((void**)&wl1lo, g_wl1lo);
    cudaGetSymbolAddress((void**)&wr1hi, g_wr1hi); cudaGetSymbolAddress((void**)&wr1lo, g_wr1lo);
    cudaGetSymbolAddress((void**)&wl2hi, g_wl2hi); cudaGetSymbolAddress((void**)&wl2lo, g_wl2lo);
    cudaGetSymbolAddress((void**)&wr2hi, g_wr2hi); cudaGetSymbolAddress((void**)&wr2lo, g_wr2lo);
    cudaGetSymbolAddress((void**)&hhi,   g_hhi);   cudaGetSymbolAddress((void**)&hlo,   g_hlo);
    cudaGetSymbolAddress((void**)&mhi,   g_mhi);   cudaGetSymbolAddress((void**)&mlo,   g_mlo);
    cudaGetSymbolAddress((void**)&o1hi,  g_o1hi);  cudaGetSymbolAddress((void**)&o1lo,  g_o1lo);

    // Static side stream + events (created on first, uncaptured call).
    static cudaStream_t s2 = nullptr;
    static cudaEvent_t eH = nullptr, eG1a = nullptr, eG1b = nullptr;
    static cudaEvent_t eO1 = nullptr, eG2a = nullptr, eG2b = nullptr;
    if (!s2) {
        cudaStreamCreateWithFlags(&s2, cudaStreamNonBlocking);
        cudaEventCreateWithFlags(&eH,   cudaEventDisableTiming);
        cudaEventCreateWithFlags(&eG1a, cudaEventDisableTiming);
        cudaEventCreateWithFlags(&eG1b, cudaEventDisableTiming);
        cudaEventCreateWithFlags(&eO1,  cudaEventDisableTiming);
        cudaEventCreateWithFlags(&eG2a, cudaEventDisableTiming);
        cudaEventCreateWithFlags(&eG2b, cudaEventDisableTiming);
    }

    const int EB = (EE + 255) / 256;
    const int SPLIT_N = NN * DIN + DIN * DOUT + 4 * DOUT * DOUT;
    dim3 fgrid(DOUT / 64, (NN + 63) / 64);     // full GEMM: (4, 157)
    dim3 g0(DOUT / 64, CH0 / 64);              // chunk 0: (4, 79)
    dim3 g1(DOUT / 64, (CH1 + 63) / 64);       // chunk 1: (4, 78)

    // s2: edge decode + CSR build (fully off the critical path)
    detect_kernel<<<1, 256, 0, s2>>>(ei);
    cudaMemsetAsync(degi, 0, NN * sizeof(int), s2);
    decode_degi_kernel<<<EB, 256, 0, s2>>>(ei, src, dst, degi);
    scan_kernel<<<1, 256, 0, s2>>>(degi, off, cur, invdeg);
    fill_kernel<<<EB, 256, 0, s2>>>(src, dst, cur, csr);

    // main: split + gemm1 (h = x@W0 + b0)
    split_kernel<<<(SPLIT_N + 255) / 256, 256>>>(x, W0, Wl1, Wr1, Wl2, Wr2);
    gemm_mma<DIN, true, false, false, false, true><<<fgrid, 128>>>(
        xhi, xlo, w0hi, w0lo, b0, nullptr, nullptr, h, hhi, hlo, NN);
    cudaEventRecord(eH, 0);

    // s2: gather1 in two chunks (one block per node!)
    cudaStreamWaitEvent(s2, eH, 0);
    gather_kernel<<<CH0, 64, 0, s2>>>(h, csr, off, degi, invdeg, mhi, mlo, 0);
    cudaEventRecord(eG1a, s2);
    gather_kernel<<<CH1, 64, 0, s2>>>(h, csr, off, degi, invdeg, mhi, mlo, CH0);
    cudaEventRecord(eG1b, s2);

    // main: tmp1 = h@Wr1 (overlaps gathers), then chunked combines
    gemm_mma<DOUT, false, false, false, false, false><<<fgrid, 128>>>(
        hhi, hlo, wr1hi, wr1lo, nullptr, nullptr, nullptr, tmp, nullptr, nullptr, NN);
    cudaStreamWaitEvent(0, eG1a, 0);
    gemm_mma<DOUT, true, true, true, true, true><<<g0, 128>>>(
        mhi, mlo, wl1hi, wl1lo, bl1, tmp, h, out1, o1hi, o1lo, CH0);
    cudaStreamWaitEvent(0, eG1b, 0);
    gemm_mma<DOUT, true, true, true, true, true><<<g1, 128>>>(
        mhi + (size_t)CH0 * DOUT, mlo + (size_t)CH0 * DOUT, wl1hi, wl1lo,
        bl1, tmp + (size_t)CH0 * DOUT, h + (size_t)CH0 * DOUT,
        out1 + (size_t)CH0 * DOUT, o1hi + (size_t)CH0 * DOUT, o1lo + (size_t)CH0 * DOUT, CH1);
    cudaEventRecord(eO1, 0);

    // s2: gather2 in two chunks (needs complete out1)
    cudaStreamWaitEvent(s2, eO1, 0);
    gather_kernel<<<CH0, 64, 0, s2>>>(out1, csr, off, degi, invdeg, mhi, mlo, 0);
    cudaEventRecord(eG2a, s2);
    gather_kernel<<<CH1, 64, 0, s2>>>(out1, csr, off, degi, invdeg, mhi, mlo, CH0);
    cudaEventRecord(eG2b, s2);

    // main: tmp2 = out1@Wr2 (overlaps gathers), then chunked combines
    gemm_mma<DOUT, false, false, false, false, false><<<fgrid, 128>>>(
        o1hi, o1lo, wr2hi, wr2lo, nullptr, nullptr, nullptr, tmp, nullptr, nullptr, NN);
    cudaStreamWaitEvent(0, eG2a, 0);
    gemm_mma<DOUT, true, true, false, true, false><<<g0, 128>>>(
        mhi, mlo, wl2hi, wl2lo, bl2, tmp, out1, out2, nullptr, nullptr, CH0);
    cudaStreamWaitEvent(0, eG2b, 0);
    gemm_mma<DOUT, true, true, false, true, false><<<g1, 128>>>(
        mhi + (size_t)CH0 * DOUT, mlo + (size_t)CH0 * DOUT, wl2hi, wl2lo,
        bl2, tmp + (size_t)CH0 * DOUT, out1 + (size_t)CH0 * DOUT,
        out2 + (size_t)CH0 * DOUT, nullptr, nullptr, CH1);
}